// round 9
// baseline (speedup 1.0000x reference)
#include <cuda_runtime.h>

// ============================================================================
// AttentionObstacleEncoder via bf16 mma.sync.m16n8k16, 3-term hi/lo split.
// R8: ldmatrix (LDSM) for all smem MMA fragments; V stored pre-split packed
// bf16 (u16) so PV has zero inner-loop CVT; batched weight uint4 loads.
// One CTA (512 thr) per batch element; weights folded+packed by prep kernels.
// ============================================================================

typedef unsigned int u32;
typedef unsigned short u16;

#define LDW  132    // u32-word row stride, packed [64][256] arrays (132%32==4)
#define LDWK 36     // u32-word row stride, packed [64][64] arrays  (36%32==4)
#define LDF  68     // fp32 row stride for scores buffer
#define LDO  260    // fp32 row stride for OutT

// smem word offsets
#define OFF_THH  0        // t hi packed  [64][LDW] = 8448 words
#define OFF_THL  8448
#define OFF_QHH  16896    // Q/ctx hi packed
#define OFF_QHL  25344
#define OFF_KHH  33792    // K_h hi packed [64][LDWK] = 2304 words
#define OFF_KHL  36096
#define OFF_PHH  38400    // P packed
#define OFF_PHL  40704
#define OFF_VHH  43008    // V_h hi packed [64 n][LDWK] (u16-addressed, stride 72)
#define OFF_VHL  45312
#define OFF_S    47616    // scores fp32 [64][LDF] = 4352 (+ scratch alias)
#define OFF_OUT  0        // OutT fp32 [64][LDO] = 16640, aliases dead T region
#define SMEM_WORDS 51968
#define SMEM_BYTES (SMEM_WORDS * 4)   // 207872

// scratch sub-offsets inside S region (floats)
#define WS_PS   0
#define WS_PM   512
#define WS_G    1024
#define WS_T1   1536
#define WS_A1   2048
#define WS_T2   2304
#define WS_RED  2816
#define WS_OBS  2848
#define WS_W1   3104     // ends 4128 <= 4352

// device scratch
__device__ float g_wf[3 * 65536];        // w2@{wq,wk,wv} fp32 (q pre-scaled 1/8)
__device__ float g_posb[3 * 16384];      // [(pos+b2)@wx + bx] per-row bias
__device__ uint4 g_wr[4 * 16384];        // bf16 hi/lo packed: {wq',wk',wv',wo}

__device__ __forceinline__ u32 packbf(float x0, float x1) {
    u32 r; asm("cvt.rn.bf16x2.f32 %0, %2, %1;" : "=r"(r) : "f"(x0), "f"(x1));
    return r;    // low = bf16(x0), high = bf16(x1)
}
__device__ __forceinline__ void bsplit(float x0, float x1, u32& hw, u32& lw) {
    hw = packbf(x0, x1);
    float h0 = __uint_as_float(hw << 16);
    float h1 = __uint_as_float(hw & 0xffff0000u);
    lw = packbf(x0 - h0, x1 - h1);
}
__device__ __forceinline__ void mmab(float* c, u32 a0, u32 a1, u32 a2, u32 a3,
                                     u32 b0, u32 b1) {
    asm("mma.sync.aligned.m16n8k16.row.col.f32.bf16.bf16.f32 "
        "{%0,%1,%2,%3},{%4,%5,%6,%7},{%8,%9},{%0,%1,%2,%3};"
        : "+f"(c[0]), "+f"(c[1]), "+f"(c[2]), "+f"(c[3])
        : "r"(a0), "r"(a1), "r"(a2), "r"(a3), "r"(b0), "r"(b1));
}
__device__ __forceinline__ void mmab3(float* c, const u32* ah, const u32* al,
                                      u32 bh0, u32 bh1, u32 bl0, u32 bl1) {
    mmab(c, ah[0], ah[1], ah[2], ah[3], bl0, bl1);
    mmab(c, al[0], al[1], al[2], al[3], bh0, bh1);
    mmab(c, ah[0], ah[1], ah[2], ah[3], bh0, bh1);
}
__device__ __forceinline__ u32 s2u(const void* p) {
    return (u32)__cvta_generic_to_shared(p);
}
__device__ __forceinline__ void ldsm4(u32 addr, u32* r) {
    asm volatile("ldmatrix.sync.aligned.m8n8.x4.shared.b16 {%0,%1,%2,%3}, [%4];"
        : "=r"(r[0]), "=r"(r[1]), "=r"(r[2]), "=r"(r[3]) : "r"(addr));
}
__device__ __forceinline__ void ldsm2(u32 addr, u32* r) {
    asm volatile("ldmatrix.sync.aligned.m8n8.x2.shared.b16 {%0,%1}, [%2];"
        : "=r"(r[0]), "=r"(r[1]) : "r"(addr));
}

// ============================================================================
// Prep kernels (per launch, deterministic)
// ============================================================================

__global__ void fold_k(const float* __restrict__ w2, const float* __restrict__ wq,
                       const float* __restrict__ wk, const float* __restrict__ wv)
{
    int m = blockIdx.x >> 8, k = blockIdx.x & 255, c = threadIdx.x;
    const float* wx = (m == 0) ? wq : (m == 1) ? wk : wv;
    float acc = 0.0f;
#pragma unroll 8
    for (int d = 0; d < 256; d++)
        acc = fmaf(__ldg(w2 + k * 256 + d), __ldg(wx + d * 256 + c), acc);
    if (m == 0) acc *= 0.125f;
    g_wf[m * 65536 + k * 256 + c] = acc;
}

__global__ void posfold_k(const float* __restrict__ pos, const float* __restrict__ b2,
                          const float* __restrict__ wq, const float* __restrict__ wk,
                          const float* __restrict__ wv, const float* __restrict__ bq,
                          const float* __restrict__ bk, const float* __restrict__ bv)
{
    int m = blockIdx.x >> 6, n = blockIdx.x & 63, c = threadIdx.x;
    const float* wx = (m == 0) ? wq : (m == 1) ? wk : wv;
    const float* bx = (m == 0) ? bq : (m == 1) ? bk : bv;
    float acc = __ldg(bx + c);
#pragma unroll 8
    for (int d = 0; d < 256; d++)
        acc = fmaf(__ldg(pos + n * 256 + d) + __ldg(b2 + d), __ldg(wx + d * 256 + c), acc);
    if (m == 0) acc *= 0.125f;
    g_posb[m * 16384 + n * 256 + c] = acc;
}

__global__ void pack_k(const float* __restrict__ wo)
{
    int idx = blockIdx.x * 256 + threadIdx.x;   // 0 .. 65535
    int m = idx >> 14;
    int u = idx & 16383;
    int ntile = u >> 9;
    int s = (u >> 5) & 15;
    int lane = u & 31;
    int g = lane >> 2, t = lane & 3;
    int n = ntile * 8 + g;
    int k0 = s * 16 + t * 2;
    const float* W = (m < 3) ? (g_wf + m * 65536) : wo;
    float f0 = W[k0 * 256 + n];
    float f1 = W[(k0 + 1) * 256 + n];
    float f2 = W[(k0 + 8) * 256 + n];
    float f3 = W[(k0 + 9) * 256 + n];
    uint4 r;
    bsplit(f0, f1, r.x, r.z);
    bsplit(f2, f3, r.y, r.w);
    g_wr[idx] = r;
}

// ============================================================================
// Device GEMM pieces
// ============================================================================

// Big GEMM: Out[64][256] = T(packed) @ Wp + bias.
template<bool PACKOUT>
__device__ __forceinline__ void gemm_big(
    const u32* Ah, const u32* Al, const uint4* __restrict__ Wp,
    const float* __restrict__ biasRows, const float* __restrict__ biasVec,
    u32* Ohh, u32* Ohl, float* Ofp)
{
    const int wid = threadIdx.x >> 5, lane = threadIdx.x & 31;
    const int g = lane >> 2, t = lane & 3;
    const int m0 = (wid & 3) << 4;
    const int ncol = wid >> 2;
    const int ntbase = ncol << 3;
    const int lr = lane & 15, hb = lane >> 4;

    const u32 aH = s2u(Ah + (m0 + lr) * LDW + (hb << 2));
    const u32 aL = s2u(Al + (m0 + lr) * LDW + (hb << 2));

    float c[8][4];
#pragma unroll
    for (int i = 0; i < 8; i++)
#pragma unroll
        for (int j = 0; j < 4; j++) c[i][j] = 0.0f;

#pragma unroll 2
    for (int s = 0; s < 16; s++) {
        u32 ah[4], al[4];
        ldsm4(aH + (s << 5), ah);
        ldsm4(aL + (s << 5), al);
        uint4 w[8];
#pragma unroll
        for (int i = 0; i < 8; i++)
            w[i] = Wp[((ntbase + i) << 9) + (s << 5) + lane];
#pragma unroll
        for (int i = 0; i < 8; i++)
            mmab3(c[i], ah, al, w[i].x, w[i].y, w[i].z, w[i].w);
    }

#pragma unroll
    for (int nt = 0; nt < 8; nt++) {
        int col = (ncol << 6) + (nt << 3) + (t << 1);
        if (PACKOUT) {
            float2 bA = *(const float2*)(biasRows + (m0 + g) * 256 + col);
            float2 bB = *(const float2*)(biasRows + (m0 + 8 + g) * 256 + col);
            u32 hw, lw;
            bsplit(c[nt][0] + bA.x, c[nt][1] + bA.y, hw, lw);
            Ohh[(m0 + g) * LDW + (col >> 1)] = hw;
            Ohl[(m0 + g) * LDW + (col >> 1)] = lw;
            bsplit(c[nt][2] + bB.x, c[nt][3] + bB.y, hw, lw);
            Ohh[(m0 + 8 + g) * LDW + (col >> 1)] = hw;
            Ohl[(m0 + 8 + g) * LDW + (col >> 1)] = lw;
        } else {
            float2 bb = *(const float2*)(biasVec + col);
            *(float2*)(Ofp + (m0 + g) * LDO + col) =
                make_float2(c[nt][0] + bb.x, c[nt][1] + bb.y);
            *(float2*)(Ofp + (m0 + 8 + g) * LDO + col) =
                make_float2(c[nt][2] + bb.x, c[nt][3] + bb.y);
        }
    }
}

// Per-head K/V: warps 0-7 -> K_h packed (word writes); warps 8-15 -> V_h
// packed bf16 stored TRANSPOSED as B-matrix rows=headcol, cols=seq (u16 writes).
__device__ __forceinline__ void gemm_kv(
    const u32* Ah, const u32* Al, int h,
    u32* Khh, u32* Khl, u16* Vhh16, u16* Vhl16)
{
    const int wid = threadIdx.x >> 5, lane = threadIdx.x & 31;
    const int g = lane >> 2, t = lane & 3;
    const int lw_ = wid & 7, isV = wid >> 3;
    const int m0 = (lw_ & 3) << 4;
    const int ncol2 = lw_ >> 2;
    const uint4* __restrict__ Wp = g_wr + ((1 + isV) << 14);
    const float* __restrict__ biasRows = g_posb + ((1 + isV) << 14);
    const int lr = lane & 15, hb = lane >> 4;

    const u32 aH = s2u(Ah + (m0 + lr) * LDW + (hb << 2));
    const u32 aL = s2u(Al + (m0 + lr) * LDW + (hb << 2));

    float c[4][4];
#pragma unroll
    for (int i = 0; i < 4; i++)
#pragma unroll
        for (int j = 0; j < 4; j++) c[i][j] = 0.0f;

#pragma unroll 2
    for (int s = 0; s < 16; s++) {
        u32 ah[4], al[4];
        ldsm4(aH + (s << 5), ah);
        ldsm4(aL + (s << 5), al);
        uint4 w[4];
#pragma unroll
        for (int i = 0; i < 4; i++) {
            int ntg = (h << 3) + (ncol2 << 2) + i;
            w[i] = Wp[(ntg << 9) + (s << 5) + lane];
        }
#pragma unroll
        for (int i = 0; i < 4; i++)
            mmab3(c[i], ah, al, w[i].x, w[i].y, w[i].z, w[i].w);
    }

#pragma unroll
    for (int nt = 0; nt < 4; nt++) {
        int nl = (ncol2 << 5) + (nt << 3) + (t << 1);
        int colg = (h << 6) + nl;
        float2 bA = *(const float2*)(biasRows + (m0 + g) * 256 + colg);
        float2 bB = *(const float2*)(biasRows + (m0 + 8 + g) * 256 + colg);
        if (!isV) {
            u32 hw, lww;
            bsplit(c[nt][0] + bA.x, c[nt][1] + bA.y, hw, lww);
            Khh[(m0 + g) * LDWK + (nl >> 1)] = hw;
            Khl[(m0 + g) * LDWK + (nl >> 1)] = lww;
            bsplit(c[nt][2] + bB.x, c[nt][3] + bB.y, hw, lww);
            Khh[(m0 + 8 + g) * LDWK + (nl >> 1)] = hw;
            Khl[(m0 + 8 + g) * LDWK + (nl >> 1)] = lww;
        } else {
            int m = m0 + g;
            u32 hw, lww;
            bsplit(c[nt][0] + bA.x, c[nt][1] + bA.y, hw, lww);   // cols nl, nl+1 @ row m
            Vhh16[nl * 72 + m]       = (u16)hw;
            Vhh16[(nl + 1) * 72 + m] = (u16)(hw >> 16);
            Vhl16[nl * 72 + m]       = (u16)lww;
            Vhl16[(nl + 1) * 72 + m] = (u16)(lww >> 16);
            bsplit(c[nt][2] + bB.x, c[nt][3] + bB.y, hw, lww);   // @ row m+8
            Vhh16[nl * 72 + m + 8]       = (u16)hw;
            Vhh16[(nl + 1) * 72 + m + 8] = (u16)(hw >> 16);
            Vhl16[nl * 72 + m + 8]       = (u16)lww;
            Vhl16[(nl + 1) * 72 + m + 8] = (u16)(lww >> 16);
        }
    }
}

// scores = Q_h(packed) @ K_h(packed)^T -> Ss fp32.  All fragments via LDSM.
__device__ __forceinline__ void gemm_scores(
    const u32* Qhh, const u32* Qhl, int h,
    const u32* Khh, const u32* Khl, float* Ss)
{
    const int wid = threadIdx.x >> 5, lane = threadIdx.x & 31;
    const int g = lane >> 2, t = lane & 3;
    const int m0 = (wid & 3) << 4;
    const int ncol = wid >> 2;
    const int lr = lane & 15, hb = lane >> 4;

    const u32 aH = s2u(Qhh + (m0 + lr) * LDW + (h << 5) + (hb << 2));
    const u32 aL = s2u(Qhl + (m0 + lr) * LDW + (h << 5) + (hb << 2));
    const int brow = (ncol << 4) + (lane & 7);
    const int boff = ((lane >> 3) & 1) << 2;
    const u32 bH0 = s2u(Khh + brow * LDWK + boff);
    const u32 bL0 = s2u(Khl + brow * LDWK + boff);
    const u32 bH8 = s2u(Khh + (brow + 8) * LDWK + boff);
    const u32 bL8 = s2u(Khl + (brow + 8) * LDWK + boff);

    float c[2][4];
#pragma unroll
    for (int i = 0; i < 2; i++)
#pragma unroll
        for (int j = 0; j < 4; j++) c[i][j] = 0.0f;

#pragma unroll
    for (int s = 0; s < 4; s++) {
        u32 ah[4], al[4], kh0[2], kl0[2], kh8[2], kl8[2];
        ldsm4(aH + (s << 5), ah);
        ldsm4(aL + (s << 5), al);
        ldsm2(bH0 + (s << 5), kh0);
        ldsm2(bL0 + (s << 5), kl0);
        ldsm2(bH8 + (s << 5), kh8);
        ldsm2(bL8 + (s << 5), kl8);
        mmab3(c[0], ah, al, kh0[0], kh0[1], kl0[0], kl0[1]);
        mmab3(c[1], ah, al, kh8[0], kh8[1], kl8[0], kl8[1]);
    }

#pragma unroll
    for (int nt = 0; nt < 2; nt++) {
        int n0 = (ncol << 4) + (nt << 3) + (t << 1);
        *(float2*)(Ss + (m0 + g) * LDF + n0)     = make_float2(c[nt][0], c[nt][1]);
        *(float2*)(Ss + (m0 + 8 + g) * LDF + n0) = make_float2(c[nt][2], c[nt][3]);
    }
}

// ctx_h = P(packed) @ V_h(packed) -> packed into Q region cols [64h,+64).
__device__ __forceinline__ void gemm_pv(
    const u32* Phh, const u32* Phl, const u32* Vhh, const u32* Vhl, int h,
    u32* Qhh, u32* Qhl)
{
    const int wid = threadIdx.x >> 5, lane = threadIdx.x & 31;
    const int g = lane >> 2, t = lane & 3;
    const int m0 = (wid & 3) << 4;
    const int ncol = wid >> 2;
    const int lr = lane & 15, hb = lane >> 4;

    const u32 aH = s2u(Phh + (m0 + lr) * LDWK + (hb << 2));
    const u32 aL = s2u(Phl + (m0 + lr) * LDWK + (hb << 2));
    const int brow = (ncol << 4) + (lane & 7);
    const int boff = ((lane >> 3) & 1) << 2;
    const u32 bH0 = s2u(Vhh + brow * LDWK + boff);
    const u32 bL0 = s2u(Vhl + brow * LDWK + boff);
    const u32 bH8 = s2u(Vhh + (brow + 8) * LDWK + boff);
    const u32 bL8 = s2u(Vhl + (brow + 8) * LDWK + boff);

    float c[2][4];
#pragma unroll
    for (int i = 0; i < 2; i++)
#pragma unroll
        for (int j = 0; j < 4; j++) c[i][j] = 0.0f;

#pragma unroll
    for (int s = 0; s < 4; s++) {
        u32 ah[4], al[4], vh0[2], vl0[2], vh8[2], vl8[2];
        ldsm4(aH + (s << 5), ah);
        ldsm4(aL + (s << 5), al);
        ldsm2(bH0 + (s << 5), vh0);
        ldsm2(bL0 + (s << 5), vl0);
        ldsm2(bH8 + (s << 5), vh8);
        ldsm2(bL8 + (s << 5), vl8);
        mmab3(c[0], ah, al, vh0[0], vh0[1], vl0[0], vl0[1]);
        mmab3(c[1], ah, al, vh8[0], vh8[1], vl8[0], vl8[1]);
    }

#pragma unroll
    for (int nt = 0; nt < 2; nt++) {
        int coll = (ncol << 4) + (nt << 3) + (t << 1);
        int wrd = (h << 5) + (coll >> 1);
        u32 hw, lw;
        bsplit(c[nt][0], c[nt][1], hw, lw);
        Qhh[(m0 + g) * LDW + wrd] = hw;
        Qhl[(m0 + g) * LDW + wrd] = lw;
        bsplit(c[nt][2], c[nt][3], hw, lw);
        Qhh[(m0 + 8 + g) * LDW + wrd] = hw;
        Qhl[(m0 + 8 + g) * LDW + wrd] = lw;
    }
}

// ============================================================================
__global__ void __launch_bounds__(512, 1)
enc_kernel(const float* __restrict__ obstacles, const int* __restrict__ lengths,
           const float* __restrict__ w1, const float* __restrict__ b1,
           const float* __restrict__ bo,
           const float* __restrict__ g1w, const float* __restrict__ g1b,
           const float* __restrict__ g2w, const float* __restrict__ g2b,
           const float* __restrict__ ln_g, const float* __restrict__ ln_b,
           float* __restrict__ out)
{
    extern __shared__ float sm[];
    u32* Thh = (u32*)(sm + OFF_THH);
    u32* Thl = (u32*)(sm + OFF_THL);
    u32* Qhh = (u32*)(sm + OFF_QHH);
    u32* Qhl = (u32*)(sm + OFF_QHL);
    u32* Khh = (u32*)(sm + OFF_KHH);
    u32* Khl = (u32*)(sm + OFF_KHL);
    u32* Phh = (u32*)(sm + OFF_PHH);
    u32* Phl = (u32*)(sm + OFF_PHL);
    u32* Vhh = (u32*)(sm + OFF_VHH);
    u32* Vhl = (u32*)(sm + OFF_VHL);
    u16* Vhh16 = (u16*)Vhh;
    u16* Vhl16 = (u16*)Vhl;
    float* Ss  = sm + OFF_S;
    float* ws  = sm + OFF_S;      // scratch alias (phase-disjoint)
    float* OutT = sm + OFF_OUT;   // aliases dead T region

    const int b   = blockIdx.x;
    const int tid = threadIdx.x;
    const int len = lengths[b];
    const int wid = tid >> 5, lane = tid & 31;

    // ---- stage w1 + obstacles ----
    if (tid < 256) {
        *(float4*)(ws + WS_W1 + (tid << 2)) = *(const float4*)(w1 + (tid << 2));
        ws[WS_OBS + tid] = obstacles[b * 256 + tid];
    }
    __syncthreads();

    // ---- phase 1: t = relu(obs @ w1 + b1) -> packed bf16 hi/lo ----
    {
        int cp = tid & 127, q = tid >> 7;
        int c0 = cp << 1;
        float wa0 = ws[WS_W1 + c0],       wa1 = ws[WS_W1 + c0 + 1];
        float wb0 = ws[WS_W1 + 256 + c0], wb1 = ws[WS_W1 + 256 + c0 + 1];
        float wc0 = ws[WS_W1 + 512 + c0], wc1 = ws[WS_W1 + 512 + c0 + 1];
        float wd0 = ws[WS_W1 + 768 + c0], wd1 = ws[WS_W1 + 768 + c0 + 1];
        float bb0 = b1[c0], bb1 = b1[c0 + 1];
        int n0 = q << 4;
#pragma unroll 4
        for (int n = n0; n < n0 + 16; n++) {
            float4 o = *(const float4*)(ws + WS_OBS + (n << 2));
            float v0 = fmaf(o.x, wa0, fmaf(o.y, wb0, fmaf(o.z, wc0, fmaf(o.w, wd0, bb0))));
            float v1 = fmaf(o.x, wa1, fmaf(o.y, wb1, fmaf(o.z, wc1, fmaf(o.w, wd1, bb1))));
            v0 = fmaxf(v0, 0.0f); v1 = fmaxf(v1, 0.0f);
            u32 hw, lw;
            bsplit(v0, v1, hw, lw);
            Thh[n * LDW + cp] = hw;
            Thl[n * LDW + cp] = lw;
        }
    }
    __syncthreads();

    // ---- Q = t @ wq' + posbq (1/8 folded), packed ----
    gemm_big<true>(Thh, Thl, g_wr, g_posb, nullptr, Qhh, Qhl, nullptr);
    __syncthreads();

    // ---- attention heads ----
#pragma unroll 1
    for (int h = 0; h < 4; h++) {
        gemm_kv(Thh, Thl, h, Khh, Khl, Vhh16, Vhl16);
        __syncthreads();

        gemm_scores(Qhh, Qhl, h, Khh, Khl, Ss);
        __syncthreads();

        // masked softmax: warp wid owns rows 4wid..+3; lane owns cols 2l,2l+1
        {
            bool va = (lane << 1) < len;
            bool vb = ((lane << 1) + 1) < len;
#pragma unroll
            for (int rr = 0; rr < 4; rr++) {
                int r = (wid << 2) + rr;
                float2 x = *(const float2*)(Ss + r * LDF + (lane << 1));
                float m = fmaxf(va ? x.x : -3.4e38f, vb ? x.y : -3.4e38f);
#pragma unroll
                for (int off = 16; off; off >>= 1)
                    m = fmaxf(m, __shfl_xor_sync(0xffffffffu, m, off));
                float e0 = va ? __expf(x.x - m) : 0.0f;
                float e1 = vb ? __expf(x.y - m) : 0.0f;
                float s = e0 + e1;
#pragma unroll
                for (int off = 16; off; off >>= 1)
                    s += __shfl_xor_sync(0xffffffffu, s, off);
                float inv = __frcp_rn(s);
                u32 hw, lw;
                bsplit(e0 * inv, e1 * inv, hw, lw);
                Phh[r * LDWK + lane] = hw;
                Phl[r * LDWK + lane] = lw;
            }
        }
        __syncthreads();

        gemm_pv(Phh, Phl, Vhh, Vhl, h, Qhh, Qhl);
        __syncthreads();
    }

    // ---- out = ctx @ wo + bo -> OutT fp32 ----
    gemm_big<false>(Qhh, Qhl, g_wr + 3 * 16384, nullptr, bo, nullptr, nullptr, OutT);
    __syncthreads();

    // ---- masked mean/max pool ----
    {
        int col = tid & 255, half = tid >> 8;
        int mid = (len + 1) >> 1;
        int nb = half ? mid : 0, ne = half ? len : mid;
        float s = 0.0f, mx = -3.4e38f;
        for (int n = nb; n < ne; n++) {
            float x = OutT[n * LDO + col];
            s += x; mx = fmaxf(mx, x);
        }
        ws[WS_PS + tid] = s;
        ws[WS_PM + tid] = mx;
    }
    __syncthreads();
    if (tid < 256) {
        ws[WS_G + tid]       = (ws[WS_PS + tid] + ws[WS_PS + 256 + tid]) / (float)len;
        ws[WS_G + 256 + tid] = fmaxf(ws[WS_PM + tid], ws[WS_PM + 256 + tid]);
    }
    __syncthreads();

    // ---- g1 ----
    {
        int col = tid & 255, half = tid >> 8;
        float acc = 0.0f;
        int kb = half << 8;
#pragma unroll 8
        for (int k = kb; k < kb + 256; k++)
            acc = fmaf(ws[WS_G + k], g1w[k * 256 + col], acc);
        ws[WS_T1 + tid] = acc;
    }
    __syncthreads();
    if (tid < 256)
        ws[WS_A1 + tid] = fmaxf(ws[WS_T1 + tid] + ws[WS_T1 + 256 + tid] + g1b[tid], 0.0f);
    __syncthreads();

    // ---- g2 ----
    {
        int col = tid & 255, half = tid >> 8;
        float acc = 0.0f;
        int kb = half << 7;
#pragma unroll 8
        for (int k = kb; k < kb + 128; k++)
            acc = fmaf(ws[WS_A1 + k], g2w[k * 256 + col], acc);
        ws[WS_T2 + tid] = acc;
    }
    __syncthreads();
    float val = 0.0f;
    if (tid < 256)
        val = ws[WS_T2 + tid] + ws[WS_T2 + 256 + tid] + g2b[tid];

    // ---- LayerNorm ----
    float s1 = val;
#pragma unroll
    for (int off = 16; off; off >>= 1) s1 += __shfl_xor_sync(0xffffffffu, s1, off);
    if (lane == 0) ws[WS_RED + wid] = s1;
    __syncthreads();
    float mu = 0.0f;
#pragma unroll
    for (int i = 0; i < 8; i++) mu += ws[WS_RED + i];
    mu *= (1.0f / 256.0f);
    __syncthreads();

    float d0 = val - mu;
    float s2 = d0 * d0;
#pragma unroll
    for (int off = 16; off; off >>= 1) s2 += __shfl_xor_sync(0xffffffffu, s2, off);
    if (lane == 0) ws[WS_RED + wid] = s2;
    __syncthreads();
    float var = 0.0f;
#pragma unroll
    for (int i = 0; i < 8; i++) var += ws[WS_RED + i];
    var *= (1.0f / 256.0f);

    if (tid < 256)
        out[b * 256 + tid] = d0 * rsqrtf(var + 1e-5f) * ln_g[tid] + ln_b[tid];
}

// ---------------------------------------------------------------------------
extern "C" void kernel_launch(void* const* d_in, const int* in_sizes, int n_in,
                              void* d_out, int out_size)
{
    const float* obstacles = (const float*)d_in[0];
    const int*   lengths   = (const int*)d_in[1];
    const float* w1   = (const float*)d_in[2];
    const float* b1   = (const float*)d_in[3];
    const float* w2   = (const float*)d_in[4];
    const float* b2   = (const float*)d_in[5];
    const float* pos  = (const float*)d_in[6];
    const float* wq   = (const float*)d_in[7];
    const float* bq   = (const float*)d_in[8];
    const float* wk   = (const float*)d_in[9];
    const float* bk   = (const float*)d_in[10];
    const float* wv   = (const float*)d_in[11];
    const float* bv   = (const float*)d_in[12];
    const float* wo   = (const float*)d_in[13];
    const float* bo   = (const float*)d_in[14];
    const float* g1w  = (const float*)d_in[15];
    const float* g1b  = (const float*)d_in[16];
    const float* g2w  = (const float*)d_in[17];
    const float* g2b  = (const float*)d_in[18];
    const float* ln_g = (const float*)d_in[19];
    const float* ln_b = (const float*)d_in[20];
    float* out = (float*)d_out;

    const int B = in_sizes[1];

    fold_k<<<768, 256>>>(w2, wq, wk, wv);
    posfold_k<<<192, 256>>>(pos, b2, wq, wk, wv, bq, bk, bv);
    pack_k<<<256, 256>>>(wo);

    cudaFuncSetAttribute(enc_kernel, cudaFuncAttributeMaxDynamicSharedMemorySize, SMEM_BYTES);
    enc_kernel<<<B, 512, SMEM_BYTES>>>(
        obstacles, lengths, w1, b1, bo,
        g1w, g1b, g2w, g2b, ln_g, ln_b, out);
}

// round 12
// speedup vs baseline: 1.2240x; 1.2240x over previous
#include <cuda_runtime.h>

// ============================================================================
// AttentionObstacleEncoder via bf16 mma.sync.m16n8k16, 3-term hi/lo split.
// R11 = R10 (length-adaptive tiling), re-audited + cleaned, resubmitted after
// infra failure. mt = ceil(len/16); all GEMMs restrict seq(m) to mt tiles and
// re-shape the warp->(m,n) map so all 16 warps stay busy at small mt:
//   mt==1: 1 m-tile x 16 n-warps (NT=2)   mt==2: 2 x 8 (NT=4)
//   mt>=3: 4 x 4 (NT=8, dead m-warps masked)
// Scores: m & n tiles masked; PV: m-tiles + k-slabs masked. Skipped rows are
// never read downstream (pool masks to len). Used-output arithmetic is
// bit-identical to the unmasked kernel.
// ============================================================================

typedef unsigned int u32;
typedef unsigned short u16;

#define LDW  132    // u32-word row stride, packed [64][256] arrays (132%32==4)
#define LDWK 36     // u32-word row stride, packed [64][64] arrays  (36%32==4)
#define LDF  68     // fp32 row stride for scores buffer
#define LDO  260    // fp32 row stride for OutT

// smem word offsets
#define OFF_THH  0        // t hi packed  [64][LDW] = 8448 words
#define OFF_THL  8448
#define OFF_QHH  16896    // Q/ctx hi packed
#define OFF_QHL  25344
#define OFF_KHH  33792    // K_h hi packed [64][LDWK] = 2304 words
#define OFF_KHL  36096
#define OFF_PHH  38400    // P packed
#define OFF_PHL  40704
#define OFF_VHH  43008    // V_h hi packed (u16-addressed, stride 72)
#define OFF_VHL  45312
#define OFF_S    47616    // scores fp32 [64][LDF] = 4352 (+ scratch alias)
#define OFF_OUT  0        // OutT fp32 [64][LDO], aliases dead T region
#define SMEM_WORDS 51968
#define SMEM_BYTES (SMEM_WORDS * 4)   // 207872

// scratch sub-offsets inside S region (floats)
#define WS_PS   0
#define WS_PM   512
#define WS_G    1024
#define WS_T1   1536
#define WS_A1   2048
#define WS_T2   2304
#define WS_RED  2816
#define WS_OBS  2848
#define WS_W1   3104

// device scratch
__device__ float g_wf[3 * 65536];        // w2@{wq,wk,wv} fp32 (q pre-scaled 1/8)
__device__ float g_posb[3 * 16384];      // [(pos+b2)@wx + bx] per-row bias
__device__ uint4 g_wr[4 * 16384];        // bf16 hi/lo packed: {wq',wk',wv',wo}

__device__ __forceinline__ u32 packbf(float x0, float x1) {
    u32 r; asm("cvt.rn.bf16x2.f32 %0, %2, %1;" : "=r"(r) : "f"(x0), "f"(x1));
    return r;
}
__device__ __forceinline__ void bsplit(float x0, float x1, u32& hw, u32& lw) {
    hw = packbf(x0, x1);
    float h0 = __uint_as_float(hw << 16);
    float h1 = __uint_as_float(hw & 0xffff0000u);
    lw = packbf(x0 - h0, x1 - h1);
}
__device__ __forceinline__ void mmab(float* c, u32 a0, u32 a1, u32 a2, u32 a3,
                                     u32 b0, u32 b1) {
    asm("mma.sync.aligned.m16n8k16.row.col.f32.bf16.bf16.f32 "
        "{%0,%1,%2,%3},{%4,%5,%6,%7},{%8,%9},{%0,%1,%2,%3};"
        : "+f"(c[0]), "+f"(c[1]), "+f"(c[2]), "+f"(c[3])
        : "r"(a0), "r"(a1), "r"(a2), "r"(a3), "r"(b0), "r"(b1));
}
__device__ __forceinline__ void mmab3(float* c, const u32* ah, const u32* al,
                                      u32 bh0, u32 bh1, u32 bl0, u32 bl1) {
    mmab(c, ah[0], ah[1], ah[2], ah[3], bl0, bl1);
    mmab(c, al[0], al[1], al[2], al[3], bh0, bh1);
    mmab(c, ah[0], ah[1], ah[2], ah[3], bh0, bh1);
}
__device__ __forceinline__ u32 s2u(const void* p) {
    return (u32)__cvta_generic_to_shared(p);
}
__device__ __forceinline__ void ldsm4(u32 addr, u32* r) {
    asm volatile("ldmatrix.sync.aligned.m8n8.x4.shared.b16 {%0,%1,%2,%3}, [%4];"
        : "=r"(r[0]), "=r"(r[1]), "=r"(r[2]), "=r"(r[3]) : "r"(addr));
}
__device__ __forceinline__ void ldsm2(u32 addr, u32* r) {
    asm volatile("ldmatrix.sync.aligned.m8n8.x2.shared.b16 {%0,%1}, [%2];"
        : "=r"(r[0]), "=r"(r[1]) : "r"(addr));
}

// ============================================================================
// Prep kernels (per launch, deterministic)
// ============================================================================

__global__ void fold_k(const float* __restrict__ w2, const float* __restrict__ wq,
                       const float* __restrict__ wk, const float* __restrict__ wv)
{
    int m = blockIdx.x >> 8, k = blockIdx.x & 255, c = threadIdx.x;
    const float* wx = (m == 0) ? wq : (m == 1) ? wk : wv;
    float acc = 0.0f;
#pragma unroll 8
    for (int d = 0; d < 256; d++)
        acc = fmaf(__ldg(w2 + k * 256 + d), __ldg(wx + d * 256 + c), acc);
    if (m == 0) acc *= 0.125f;
    g_wf[m * 65536 + k * 256 + c] = acc;
}

__global__ void posfold_k(const float* __restrict__ pos, const float* __restrict__ b2,
                          const float* __restrict__ wq, const float* __restrict__ wk,
                          const float* __restrict__ wv, const float* __restrict__ bq,
                          const float* __restrict__ bk, const float* __restrict__ bv)
{
    int m = blockIdx.x >> 6, n = blockIdx.x & 63, c = threadIdx.x;
    const float* wx = (m == 0) ? wq : (m == 1) ? wk : wv;
    const float* bx = (m == 0) ? bq : (m == 1) ? bk : bv;
    float acc = __ldg(bx + c);
#pragma unroll 8
    for (int d = 0; d < 256; d++)
        acc = fmaf(__ldg(pos + n * 256 + d) + __ldg(b2 + d), __ldg(wx + d * 256 + c), acc);
    if (m == 0) acc *= 0.125f;
    g_posb[m * 16384 + n * 256 + c] = acc;
}

__global__ void pack_k(const float* __restrict__ wo)
{
    int idx = blockIdx.x * 256 + threadIdx.x;   // 0 .. 65535
    int m = idx >> 14;
    int u = idx & 16383;
    int ntile = u >> 9;
    int s = (u >> 5) & 15;
    int lane = u & 31;
    int g = lane >> 2, t = lane & 3;
    int n = ntile * 8 + g;
    int k0 = s * 16 + t * 2;
    const float* W = (m < 3) ? (g_wf + m * 65536) : wo;
    float f0 = W[k0 * 256 + n];
    float f1 = W[(k0 + 1) * 256 + n];
    float f2 = W[(k0 + 8) * 256 + n];
    float f3 = W[(k0 + 9) * 256 + n];
    uint4 r;
    bsplit(f0, f1, r.x, r.z);
    bsplit(f2, f3, r.y, r.w);
    g_wr[idx] = r;
}

// ============================================================================
// Device GEMM pieces
// ============================================================================

// Big GEMM (one warp's share): m-tile mrow, NT consecutive n-tiles at ntbase.
template<int NT, bool PACKOUT>
__device__ __forceinline__ void gemm_big_t(
    const u32* Ah, const u32* Al, const uint4* __restrict__ Wp,
    const float* __restrict__ biasRows, const float* __restrict__ biasVec,
    u32* Ohh, u32* Ohl, float* Ofp, int mrow, int ntbase, bool active)
{
    if (!active) return;
    const int lane = threadIdx.x & 31;
    const int g = lane >> 2, t = lane & 3;
    const int m0 = mrow << 4;
    const int lr = lane & 15, hb = lane >> 4;

    const u32 aH = s2u(Ah + (m0 + lr) * LDW + (hb << 2));
    const u32 aL = s2u(Al + (m0 + lr) * LDW + (hb << 2));

    float c[NT][4];
#pragma unroll
    for (int i = 0; i < NT; i++)
#pragma unroll
        for (int j = 0; j < 4; j++) c[i][j] = 0.0f;

#pragma unroll 2
    for (int s = 0; s < 16; s++) {
        u32 ah[4], al[4];
        ldsm4(aH + (s << 5), ah);
        ldsm4(aL + (s << 5), al);
        uint4 w[NT];
#pragma unroll
        for (int i = 0; i < NT; i++)
            w[i] = Wp[((ntbase + i) << 9) + (s << 5) + lane];
#pragma unroll
        for (int i = 0; i < NT; i++)
            mmab3(c[i], ah, al, w[i].x, w[i].y, w[i].z, w[i].w);
    }

#pragma unroll
    for (int nt = 0; nt < NT; nt++) {
        int col = ((ntbase + nt) << 3) + (t << 1);
        if (PACKOUT) {
            float2 bA = *(const float2*)(biasRows + (m0 + g) * 256 + col);
            float2 bB = *(const float2*)(biasRows + (m0 + 8 + g) * 256 + col);
            u32 hw, lw;
            bsplit(c[nt][0] + bA.x, c[nt][1] + bA.y, hw, lw);
            Ohh[(m0 + g) * LDW + (col >> 1)] = hw;
            Ohl[(m0 + g) * LDW + (col >> 1)] = lw;
            bsplit(c[nt][2] + bB.x, c[nt][3] + bB.y, hw, lw);
            Ohh[(m0 + 8 + g) * LDW + (col >> 1)] = hw;
            Ohl[(m0 + 8 + g) * LDW + (col >> 1)] = lw;
        } else {
            float2 bb = *(const float2*)(biasVec + col);
            *(float2*)(Ofp + (m0 + g) * LDO + col) =
                make_float2(c[nt][0] + bb.x, c[nt][1] + bb.y);
            *(float2*)(Ofp + (m0 + 8 + g) * LDO + col) =
                make_float2(c[nt][2] + bb.x, c[nt][3] + bb.y);
        }
    }
}

// KV (one warp's share): NT n-tiles at local ntl (0..7 within head h).
// isV: write V transposed pre-split u16; else K packed words.
template<int NT>
__device__ __forceinline__ void gemm_kv_t(
    const u32* Ah, const u32* Al, int h,
    u32* Khh, u32* Khl, u16* Vhh16, u16* Vhl16,
    int mrow, int ntl, bool active, int isV)
{
    if (!active) return;
    const int lane = threadIdx.x & 31;
    const int g = lane >> 2, t = lane & 3;
    const int m0 = mrow << 4;
    const uint4* __restrict__ Wp = g_wr + ((1 + isV) << 14);
    const float* __restrict__ biasRows = g_posb + ((1 + isV) << 14);
    const int lr = lane & 15, hb = lane >> 4;

    const u32 aH = s2u(Ah + (m0 + lr) * LDW + (hb << 2));
    const u32 aL = s2u(Al + (m0 + lr) * LDW + (hb << 2));

    float c[NT][4];
#pragma unroll
    for (int i = 0; i < NT; i++)
#pragma unroll
        for (int j = 0; j < 4; j++) c[i][j] = 0.0f;

#pragma unroll 2
    for (int s = 0; s < 16; s++) {
        u32 ah[4], al[4];
        ldsm4(aH + (s << 5), ah);
        ldsm4(aL + (s << 5), al);
        uint4 w[NT];
#pragma unroll
        for (int i = 0; i < NT; i++)
            w[i] = Wp[(((h << 3) + ntl + i) << 9) + (s << 5) + lane];
#pragma unroll
        for (int i = 0; i < NT; i++)
            mmab3(c[i], ah, al, w[i].x, w[i].y, w[i].z, w[i].w);
    }

#pragma unroll
    for (int nt = 0; nt < NT; nt++) {
        int nl = ((ntl + nt) << 3) + (t << 1);
        int colg = (h << 6) + nl;
        float2 bA = *(const float2*)(biasRows + (m0 + g) * 256 + colg);
        float2 bB = *(const float2*)(biasRows + (m0 + 8 + g) * 256 + colg);
        if (!isV) {
            u32 hw, lww;
            bsplit(c[nt][0] + bA.x, c[nt][1] + bA.y, hw, lww);
            Khh[(m0 + g) * LDWK + (nl >> 1)] = hw;
            Khl[(m0 + g) * LDWK + (nl >> 1)] = lww;
            bsplit(c[nt][2] + bB.x, c[nt][3] + bB.y, hw, lww);
            Khh[(m0 + 8 + g) * LDWK + (nl >> 1)] = hw;
            Khl[(m0 + 8 + g) * LDWK + (nl >> 1)] = lww;
        } else {
            int m = m0 + g;
            u32 hw, lww;
            bsplit(c[nt][0] + bA.x, c[nt][1] + bA.y, hw, lww);
            Vhh16[nl * 72 + m]       = (u16)hw;
            Vhh16[(nl + 1) * 72 + m] = (u16)(hw >> 16);
            Vhl16[nl * 72 + m]       = (u16)lww;
            Vhl16[(nl + 1) * 72 + m] = (u16)(lww >> 16);
            bsplit(c[nt][2] + bB.x, c[nt][3] + bB.y, hw, lww);
            Vhh16[nl * 72 + m + 8]       = (u16)hw;
            Vhh16[(nl + 1) * 72 + m + 8] = (u16)(hw >> 16);
            Vhl16[nl * 72 + m + 8]       = (u16)lww;
            Vhl16[(nl + 1) * 72 + m + 8] = (u16)(lww >> 16);
        }
    }
}

// scores = Q_h @ K_h^T (active warps only: m-tile & n-tile < mt).
__device__ __forceinline__ void gemm_scores(
    const u32* Qhh, const u32* Qhl, int h,
    const u32* Khh, const u32* Khl, float* Ss, int mt)
{
    const int wid = threadIdx.x >> 5, lane = threadIdx.x & 31;
    const int mrow = wid & 3, ncol = wid >> 2;
    if (mrow >= mt || ncol >= mt) return;
    const int g = lane >> 2, t = lane & 3;
    const int m0 = mrow << 4;
    const int lr = lane & 15, hb = lane >> 4;

    const u32 aH = s2u(Qhh + (m0 + lr) * LDW + (h << 5) + (hb << 2));
    const u32 aL = s2u(Qhl + (m0 + lr) * LDW + (h << 5) + (hb << 2));
    const int brow = (ncol << 4) + (lane & 7);
    const int boff = ((lane >> 3) & 1) << 2;
    const u32 bH0 = s2u(Khh + brow * LDWK + boff);
    const u32 bL0 = s2u(Khl + brow * LDWK + boff);
    const u32 bH8 = s2u(Khh + (brow + 8) * LDWK + boff);
    const u32 bL8 = s2u(Khl + (brow + 8) * LDWK + boff);

    float c[2][4];
#pragma unroll
    for (int i = 0; i < 2; i++)
#pragma unroll
        for (int j = 0; j < 4; j++) c[i][j] = 0.0f;

#pragma unroll
    for (int s = 0; s < 4; s++) {
        u32 ah[4], al[4], kh0[2], kl0[2], kh8[2], kl8[2];
        ldsm4(aH + (s << 5), ah);
        ldsm4(aL + (s << 5), al);
        ldsm2(bH0 + (s << 5), kh0);
        ldsm2(bL0 + (s << 5), kl0);
        ldsm2(bH8 + (s << 5), kh8);
        ldsm2(bL8 + (s << 5), kl8);
        mmab3(c[0], ah, al, kh0[0], kh0[1], kl0[0], kl0[1]);
        mmab3(c[1], ah, al, kh8[0], kh8[1], kl8[0], kl8[1]);
    }

#pragma unroll
    for (int nt = 0; nt < 2; nt++) {
        int n0 = (ncol << 4) + (nt << 3) + (t << 1);
        *(float2*)(Ss + (m0 + g) * LDF + n0)     = make_float2(c[nt][0], c[nt][1]);
        *(float2*)(Ss + (m0 + 8 + g) * LDF + n0) = make_float2(c[nt][2], c[nt][3]);
    }
}

// ctx_h = P @ V_h -> packed into Q region. m-tiles & k-slabs masked by mt.
__device__ __forceinline__ void gemm_pv(
    const u32* Phh, const u32* Phl, const u32* Vhh, const u32* Vhl, int h,
    u32* Qhh, u32* Qhl, int mt)
{
    const int wid = threadIdx.x >> 5, lane = threadIdx.x & 31;
    const int mrow = wid & 3, ncol = wid >> 2;
    if (mrow >= mt) return;
    const int g = lane >> 2, t = lane & 3;
    const int m0 = mrow << 4;
    const int lr = lane & 15, hb = lane >> 4;

    const u32 aH = s2u(Phh + (m0 + lr) * LDWK + (hb << 2));
    const u32 aL = s2u(Phl + (m0 + lr) * LDWK + (hb << 2));
    const int brow = (ncol << 4) + (lane & 7);
    const int boff = ((lane >> 3) & 1) << 2;
    const u32 bH0 = s2u(Vhh + brow * LDWK + boff);
    const u32 bL0 = s2u(Vhl + brow * LDWK + boff);
    const u32 bH8 = s2u(Vhh + (brow + 8) * LDWK + boff);
    const u32 bL8 = s2u(Vhl + (brow + 8) * LDWK + boff);

    float c[2][4];
#pragma unroll
    for (int i = 0; i < 2; i++)
#pragma unroll
        for (int j = 0; j < 4; j++) c[i][j] = 0.0f;

    for (int s = 0; s < mt; s++) {
        u32 ah[4], al[4], vh0[2], vl0[2], vh8[2], vl8[2];
        ldsm4(aH + (s << 5), ah);
        ldsm4(aL + (s << 5), al);
        ldsm2(bH0 + (s << 5), vh0);
        ldsm2(bL0 + (s << 5), vl0);
        ldsm2(bH8 + (s << 5), vh8);
        ldsm2(bL8 + (s << 5), vl8);
        mmab3(c[0], ah, al, vh0[0], vh0[1], vl0[0], vl0[1]);
        mmab3(c[1], ah, al, vh8[0], vh8[1], vl8[0], vl8[1]);
    }

#pragma unroll
    for (int nt = 0; nt < 2; nt++) {
        int coll = (ncol << 4) + (nt << 3) + (t << 1);
        int wrd = (h << 5) + (coll >> 1);
        u32 hw, lw;
        bsplit(c[nt][0], c[nt][1], hw, lw);
        Qhh[(m0 + g) * LDW + wrd] = hw;
        Qhl[(m0 + g) * LDW + wrd] = lw;
        bsplit(c[nt][2], c[nt][3], hw, lw);
        Qhh[(m0 + 8 + g) * LDW + wrd] = hw;
        Qhl[(m0 + 8 + g) * LDW + wrd] = lw;
    }
}

// ============================================================================
__global__ void __launch_bounds__(512, 1)
enc_kernel(const float* __restrict__ obstacles, const int* __restrict__ lengths,
           const float* __restrict__ w1, const float* __restrict__ b1,
           const float* __restrict__ bo,
           const float* __restrict__ g1w, const float* __restrict__ g1b,
           const float* __restrict__ g2w, const float* __restrict__ g2b,
           const float* __restrict__ ln_g, const float* __restrict__ ln_b,
           float* __restrict__ out)
{
    extern __shared__ float sm[];
    u32* Thh = (u32*)(sm + OFF_THH);
    u32* Thl = (u32*)(sm + OFF_THL);
    u32* Qhh = (u32*)(sm + OFF_QHH);
    u32* Qhl = (u32*)(sm + OFF_QHL);
    u32* Khh = (u32*)(sm + OFF_KHH);
    u32* Khl = (u32*)(sm + OFF_KHL);
    u32* Phh = (u32*)(sm + OFF_PHH);
    u32* Phl = (u32*)(sm + OFF_PHL);
    u32* Vhh = (u32*)(sm + OFF_VHH);
    u32* Vhl = (u32*)(sm + OFF_VHL);
    u16* Vhh16 = (u16*)Vhh;
    u16* Vhl16 = (u16*)Vhl;
    float* Ss  = sm + OFF_S;
    float* ws  = sm + OFF_S;      // scratch alias (phase-disjoint)
    float* OutT = sm + OFF_OUT;   // aliases dead T region

    const int b   = blockIdx.x;
    const int tid = threadIdx.x;
    const int len = lengths[b];
    const int mt  = (len + 15) >> 4;          // 1..4 active seq tiles
    const int wid = tid >> 5, lane = tid & 31;

    // ---- stage w1 + obstacles ----
    if (tid < 256) {
        *(float4*)(ws + WS_W1 + (tid << 2)) = *(const float4*)(w1 + (tid << 2));
        ws[WS_OBS + tid] = obstacles[b * 256 + tid];
    }
    __syncthreads();

    // ---- phase 1: t = relu(obs @ w1 + b1) -> packed bf16 hi/lo (rows < 16mt) ----
    {
        int cp = tid & 127, q = tid >> 7;
        int c0 = cp << 1;
        float wa0 = ws[WS_W1 + c0],       wa1 = ws[WS_W1 + c0 + 1];
        float wb0 = ws[WS_W1 + 256 + c0], wb1 = ws[WS_W1 + 256 + c0 + 1];
        float wc0 = ws[WS_W1 + 512 + c0], wc1 = ws[WS_W1 + 512 + c0 + 1];
        float wd0 = ws[WS_W1 + 768 + c0], wd1 = ws[WS_W1 + 768 + c0 + 1];
        float bb0 = b1[c0], bb1 = b1[c0 + 1];
        int n0 = q << 4;
        if (q < mt) {
#pragma unroll 4
            for (int n = n0; n < n0 + 16; n++) {
                float4 o = *(const float4*)(ws + WS_OBS + (n << 2));
                float v0 = fmaf(o.x, wa0, fmaf(o.y, wb0, fmaf(o.z, wc0, fmaf(o.w, wd0, bb0))));
                float v1 = fmaf(o.x, wa1, fmaf(o.y, wb1, fmaf(o.z, wc1, fmaf(o.w, wd1, bb1))));
                v0 = fmaxf(v0, 0.0f); v1 = fmaxf(v1, 0.0f);
                u32 hw, lw;
                bsplit(v0, v1, hw, lw);
                Thh[n * LDW + cp] = hw;
                Thl[n * LDW + cp] = lw;
            }
        }
    }
    __syncthreads();

    // ---- Q = t @ wq' + posbq (1/8 folded), packed, rebalanced ----
    if (mt == 1)
        gemm_big_t<2, true>(Thh, Thl, g_wr, g_posb, nullptr, Qhh, Qhl, nullptr,
                            0, wid << 1, true);
    else if (mt == 2)
        gemm_big_t<4, true>(Thh, Thl, g_wr, g_posb, nullptr, Qhh, Qhl, nullptr,
                            wid & 1, (wid >> 1) << 2, true);
    else
        gemm_big_t<8, true>(Thh, Thl, g_wr, g_posb, nullptr, Qhh, Qhl, nullptr,
                            wid & 3, (wid >> 2) << 3, (wid & 3) < mt);
    __syncthreads();

    // ---- attention heads ----
    const int lw_ = wid & 7, isV = wid >> 3;
#pragma unroll 1
    for (int h = 0; h < 4; h++) {
        if (mt == 1)
            gemm_kv_t<1>(Thh, Thl, h, Khh, Khl, Vhh16, Vhl16,
                         0, lw_, true, isV);
        else if (mt == 2)
            gemm_kv_t<2>(Thh, Thl, h, Khh, Khl, Vhh16, Vhl16,
                         lw_ & 1, (lw_ >> 1) << 1, true, isV);
        else
            gemm_kv_t<4>(Thh, Thl, h, Khh, Khl, Vhh16, Vhl16,
                         lw_ & 3, (lw_ >> 2) << 2, (lw_ & 3) < mt, isV);
        __syncthreads();

        gemm_scores(Qhh, Qhl, h, Khh, Khl, Ss, mt);
        __syncthreads();

        // masked softmax on rows < 16mt (warp wid owns rows 4wid..+3)
        if (wid < (mt << 2)) {
            bool va = (lane << 1) < len;
            bool vb = ((lane << 1) + 1) < len;
#pragma unroll
            for (int rr = 0; rr < 4; rr++) {
                int r = (wid << 2) + rr;
                float2 x = *(const float2*)(Ss + r * LDF + (lane << 1));
                float m = fmaxf(va ? x.x : -3.4e38f, vb ? x.y : -3.4e38f);
#pragma unroll
                for (int off = 16; off; off >>= 1)
                    m = fmaxf(m, __shfl_xor_sync(0xffffffffu, m, off));
                float e0 = va ? __expf(x.x - m) : 0.0f;
                float e1 = vb ? __expf(x.y - m) : 0.0f;
                float s = e0 + e1;
#pragma unroll
                for (int off = 16; off; off >>= 1)
                    s += __shfl_xor_sync(0xffffffffu, s, off);
                float inv = __frcp_rn(s);
                u32 hw, lw;
                bsplit(e0 * inv, e1 * inv, hw, lw);
                Phh[r * LDWK + lane] = hw;
                Phl[r * LDWK + lane] = lw;
            }
        }
        __syncthreads();

        gemm_pv(Phh, Phl, Vhh, Vhl, h, Qhh, Qhl, mt);
        __syncthreads();
    }

    // ---- out = ctx @ wo + bo -> OutT fp32, rebalanced ----
    if (mt == 1)
        gemm_big_t<2, false>(Qhh, Qhl, g_wr + 3 * 16384, nullptr, bo,
                             nullptr, nullptr, OutT, 0, wid << 1, true);
    else if (mt == 2)
        gemm_big_t<4, false>(Qhh, Qhl, g_wr + 3 * 16384, nullptr, bo,
                             nullptr, nullptr, OutT, wid & 1, (wid >> 1) << 2, true);
    else
        gemm_big_t<8, false>(Qhh, Qhl, g_wr + 3 * 16384, nullptr, bo,
                             nullptr, nullptr, OutT, wid & 3, (wid >> 2) << 3,
                             (wid & 3) < mt);
    __syncthreads();

    // ---- masked mean/max pool ----
    {
        int col = tid & 255, half = tid >> 8;
        int mid = (len + 1) >> 1;
        int nb = half ? mid : 0, ne = half ? len : mid;
        float s = 0.0f, mx = -3.4e38f;
        for (int n = nb; n < ne; n++) {
            float x = OutT[n * LDO + col];
            s += x; mx = fmaxf(mx, x);
        }
        ws[WS_PS + tid] = s;
        ws[WS_PM + tid] = mx;
    }
    __syncthreads();
    if (tid < 256) {
        ws[WS_G + tid]       = (ws[WS_PS + tid] + ws[WS_PS + 256 + tid]) / (float)len;
        ws[WS_G + 256 + tid] = fmaxf(ws[WS_PM + tid], ws[WS_PM + 256 + tid]);
    }
    __syncthreads();

    // ---- g1 ----
    {
        int col = tid & 255, half = tid >> 8;
        float acc = 0.0f;
        int kb = half << 8;
#pragma unroll 8
        for (int k = kb; k < kb + 256; k++)
            acc = fmaf(ws[WS_G + k], g1w[k * 256 + col], acc);
        ws[WS_T1 + tid] = acc;
    }
    __syncthreads();
    if (tid < 256)
        ws[WS_A1 + tid] = fmaxf(ws[WS_T1 + tid] + ws[WS_T1 + 256 + tid] + g1b[tid], 0.0f);
    __syncthreads();

    // ---- g2 ----
    {
        int col = tid & 255, half = tid >> 8;
        float acc = 0.0f;
        int kb = half << 7;
#pragma unroll 8
        for (int k = kb; k < kb + 128; k++)
            acc = fmaf(ws[WS_A1 + k], g2w[k * 256 + col], acc);
        ws[WS_T2 + tid] = acc;
    }
    __syncthreads();
    float val = 0.0f;
    if (tid < 256)
        val = ws[WS_T2 + tid] + ws[WS_T2 + 256 + tid] + g2b[tid];

    // ---- LayerNorm ----
    float s1 = val;
#pragma unroll
    for (int off = 16; off; off >>= 1) s1 += __shfl_xor_sync(0xffffffffu, s1, off);
    if (lane == 0) ws[WS_RED + wid] = s1;
    __syncthreads();
    float mu = 0.0f;
#pragma unroll
    for (int i = 0; i < 8; i++) mu += ws[WS_RED + i];
    mu *= (1.0f / 256.0f);
    __syncthreads();

    float d0 = val - mu;
    float s2 = d0 * d0;
#pragma unroll
    for (int off = 16; off; off >>= 1) s2 += __shfl_xor_sync(0xffffffffu, s2, off);
    if (lane == 0) ws[WS_RED + wid] = s2;
    __syncthreads();
    float var = 0.0f;
#pragma unroll
    for (int i = 0; i < 8; i++) var += ws[WS_RED + i];
    var *= (1.0f / 256.0f);

    if (tid < 256)
        out[b * 256 + tid] = d0 * rsqrtf(var + 1e-5f) * ln_g[tid] + ln_b[tid];
}

// ---------------------------------------------------------------------------
extern "C" void kernel_launch(void* const* d_in, const int* in_sizes, int n_in,
                              void* d_out, int out_size)
{
    const float* obstacles = (const float*)d_in[0];
    const int*   lengths   = (const int*)d_in[1];
    const float* w1   = (const float*)d_in[2];
    const float* b1   = (const float*)d_in[3];
    const float* w2   = (const float*)d_in[4];
    const float* b2   = (const float*)d_in[5];
    const float* pos  = (const float*)d_in[6];
    const float* wq   = (const float*)d_in[7];
    const float* bq   = (const float*)d_in[8];
    const float* wk   = (const float*)d_in[9];
    const float* bk   = (const float*)d_in[10];
    const float* wv   = (const float*)d_in[11];
    const float* bv   = (const float*)d_in[12];
    const float* wo   = (const float*)d_in[13];
    const float* bo   = (const float*)d_in[14];
    const float* g1w  = (const float*)d_in[15];
    const float* g1b  = (const float*)d_in[16];
    const float* g2w  = (const float*)d_in[17];
    const float* g2b  = (const float*)d_in[18];
    const float* ln_g = (const float*)d_in[19];
    const float* ln_b = (const float*)d_in[20];
    float* out = (float*)d_out;

    const int B = in_sizes[1];

    fold_k<<<768, 256>>>(w2, wq, wk, wv);
    posfold_k<<<192, 256>>>(pos, b2, wq, wk, wv, bq, bk, bv);
    pack_k<<<256, 256>>>(wo);

    cudaFuncSetAttribute(enc_kernel, cudaFuncAttributeMaxDynamicSharedMemorySize, SMEM_BYTES);
    enc_kernel<<<B, 512, SMEM_BYTES>>>(
        obstacles, lengths, w1, b1, bo,
        g1w, g1b, g2w, g2b, ln_g, ln_b, out);
}

// round 13
// speedup vs baseline: 1.2424x; 1.0150x over previous
#include <cuda_runtime.h>

// ============================================================================
// AttentionObstacleEncoder via bf16 mma.sync.m16n8k16, 3-term hi/lo split.
// R13: 1024 threads (32 warps) per CTA, halved per-warp tiles, for 2x the
// latency hiding (occ 25%->50%). Length-adaptive tiling kept (mt=ceil(len/16)).
// Warp maps per mt:
//   big GEMM: mt=1: 1m x 32n (NT=1); mt=2: 2 x 16 (NT=2); mt>=3: 4 x 8 (NT=4)
//   KV: 16 K-warps + 16 V-warps; mt=1: 1x8 NT=1; mt=2: 2x8 NT=1; mt>=3: 4x4 NT=2
//   scores/PV: 4m x 8n, one 16x8 tile per warp, masked by mt
// Pool/g1/g2: 4-way k/row splits; scratch relocated to dead K/V smem region.
// ============================================================================

typedef unsigned int u32;
typedef unsigned short u16;

#define LDW  132    // u32-word row stride, packed [64][256] arrays (132%32==4)
#define LDWK 36     // u32-word row stride, packed [64][64] arrays  (36%32==4)
#define LDF  68     // fp32 row stride for scores buffer
#define LDO  260    // fp32 row stride for OutT

// smem word offsets
#define OFF_THH  0        // t hi packed  [64][LDW] = 8448 words
#define OFF_THL  8448
#define OFF_QHH  16896    // Q/ctx hi packed
#define OFF_QHL  25344
#define OFF_KHH  33792    // K_h hi packed [64][LDWK] = 2304 words
#define OFF_KHL  36096
#define OFF_PHH  38400    // P packed
#define OFF_PHL  40704
#define OFF_VHH  43008    // V_h hi packed (u16-addressed, stride 72)
#define OFF_VHL  45312
#define OFF_S    47616    // scores fp32 [64][LDF] = 4352
#define OFF_OUT  0        // OutT fp32 [64][LDO], aliases dead T region
#define OFF_WS   33792    // scratch aliases K/P/V region (phase-disjoint)
#define SMEM_WORDS 51968
#define SMEM_BYTES (SMEM_WORDS * 4)   // 207872

// scratch sub-offsets (floats, relative to OFF_WS; region = 13824 words)
#define WS_PS   0        // pool partial sums [1024]
#define WS_PM   1024     // pool partial max  [1024]
#define WS_G    2048     // pooled g [512]
#define WS_T1   2560     // g1 partials [1024]
#define WS_A1   3584     // relu(g1) [256]
#define WS_T2   3840     // g2 partials [1024]
#define WS_RED  4864     // LN reduction [32]
#define WS_OBS  4896     // obstacles [256]
#define WS_W1   5152     // w1 staged [1024] -> ends 6176 <= 13824

// device scratch
__device__ float g_wf[3 * 65536];        // w2@{wq,wk,wv} fp32 (q pre-scaled 1/8)
__device__ float g_posb[3 * 16384];      // [(pos+b2)@wx + bx] per-row bias
__device__ uint4 g_wr[4 * 16384];        // bf16 hi/lo packed: {wq',wk',wv',wo}

__device__ __forceinline__ u32 packbf(float x0, float x1) {
    u32 r; asm("cvt.rn.bf16x2.f32 %0, %2, %1;" : "=r"(r) : "f"(x0), "f"(x1));
    return r;
}
__device__ __forceinline__ void bsplit(float x0, float x1, u32& hw, u32& lw) {
    hw = packbf(x0, x1);
    float h0 = __uint_as_float(hw << 16);
    float h1 = __uint_as_float(hw & 0xffff0000u);
    lw = packbf(x0 - h0, x1 - h1);
}
__device__ __forceinline__ void mmab(float* c, u32 a0, u32 a1, u32 a2, u32 a3,
                                     u32 b0, u32 b1) {
    asm("mma.sync.aligned.m16n8k16.row.col.f32.bf16.bf16.f32 "
        "{%0,%1,%2,%3},{%4,%5,%6,%7},{%8,%9},{%0,%1,%2,%3};"
        : "+f"(c[0]), "+f"(c[1]), "+f"(c[2]), "+f"(c[3])
        : "r"(a0), "r"(a1), "r"(a2), "r"(a3), "r"(b0), "r"(b1));
}
__device__ __forceinline__ void mmab3(float* c, const u32* ah, const u32* al,
                                      u32 bh0, u32 bh1, u32 bl0, u32 bl1) {
    mmab(c, ah[0], ah[1], ah[2], ah[3], bl0, bl1);
    mmab(c, al[0], al[1], al[2], al[3], bh0, bh1);
    mmab(c, ah[0], ah[1], ah[2], ah[3], bh0, bh1);
}
__device__ __forceinline__ u32 s2u(const void* p) {
    return (u32)__cvta_generic_to_shared(p);
}
__device__ __forceinline__ void ldsm4(u32 addr, u32* r) {
    asm volatile("ldmatrix.sync.aligned.m8n8.x4.shared.b16 {%0,%1,%2,%3}, [%4];"
        : "=r"(r[0]), "=r"(r[1]), "=r"(r[2]), "=r"(r[3]) : "r"(addr));
}
__device__ __forceinline__ void ldsm2(u32 addr, u32* r) {
    asm volatile("ldmatrix.sync.aligned.m8n8.x2.shared.b16 {%0,%1}, [%2];"
        : "=r"(r[0]), "=r"(r[1]) : "r"(addr));
}

// ============================================================================
// Prep kernels (per launch, deterministic)
// ============================================================================

__global__ void fold_k(const float* __restrict__ w2, const float* __restrict__ wq,
                       const float* __restrict__ wk, const float* __restrict__ wv)
{
    int m = blockIdx.x >> 8, k = blockIdx.x & 255, c = threadIdx.x;
    const float* wx = (m == 0) ? wq : (m == 1) ? wk : wv;
    float acc = 0.0f;
#pragma unroll 8
    for (int d = 0; d < 256; d++)
        acc = fmaf(__ldg(w2 + k * 256 + d), __ldg(wx + d * 256 + c), acc);
    if (m == 0) acc *= 0.125f;
    g_wf[m * 65536 + k * 256 + c] = acc;
}

__global__ void posfold_k(const float* __restrict__ pos, const float* __restrict__ b2,
                          const float* __restrict__ wq, const float* __restrict__ wk,
                          const float* __restrict__ wv, const float* __restrict__ bq,
                          const float* __restrict__ bk, const float* __restrict__ bv)
{
    int m = blockIdx.x >> 6, n = blockIdx.x & 63, c = threadIdx.x;
    const float* wx = (m == 0) ? wq : (m == 1) ? wk : wv;
    const float* bx = (m == 0) ? bq : (m == 1) ? bk : bv;
    float acc = __ldg(bx + c);
#pragma unroll 8
    for (int d = 0; d < 256; d++)
        acc = fmaf(__ldg(pos + n * 256 + d) + __ldg(b2 + d), __ldg(wx + d * 256 + c), acc);
    if (m == 0) acc *= 0.125f;
    g_posb[m * 16384 + n * 256 + c] = acc;
}

__global__ void pack_k(const float* __restrict__ wo)
{
    int idx = blockIdx.x * 256 + threadIdx.x;   // 0 .. 65535
    int m = idx >> 14;
    int u = idx & 16383;
    int ntile = u >> 9;
    int s = (u >> 5) & 15;
    int lane = u & 31;
    int g = lane >> 2, t = lane & 3;
    int n = ntile * 8 + g;
    int k0 = s * 16 + t * 2;
    const float* W = (m < 3) ? (g_wf + m * 65536) : wo;
    float f0 = W[k0 * 256 + n];
    float f1 = W[(k0 + 1) * 256 + n];
    float f2 = W[(k0 + 8) * 256 + n];
    float f3 = W[(k0 + 9) * 256 + n];
    uint4 r;
    bsplit(f0, f1, r.x, r.z);
    bsplit(f2, f3, r.y, r.w);
    g_wr[idx] = r;
}

// ============================================================================
// Device GEMM pieces
// ============================================================================

// Big GEMM (one warp's share): m-tile mrow, NT consecutive n-tiles at ntbase.
template<int NT, bool PACKOUT>
__device__ __forceinline__ void gemm_big_t(
    const u32* Ah, const u32* Al, const uint4* __restrict__ Wp,
    const float* __restrict__ biasRows, const float* __restrict__ biasVec,
    u32* Ohh, u32* Ohl, float* Ofp, int mrow, int ntbase, bool active)
{
    if (!active) return;
    const int lane = threadIdx.x & 31;
    const int g = lane >> 2, t = lane & 3;
    const int m0 = mrow << 4;
    const int lr = lane & 15, hb = lane >> 4;

    const u32 aH = s2u(Ah + (m0 + lr) * LDW + (hb << 2));
    const u32 aL = s2u(Al + (m0 + lr) * LDW + (hb << 2));

    float c[NT][4];
#pragma unroll
    for (int i = 0; i < NT; i++)
#pragma unroll
        for (int j = 0; j < 4; j++) c[i][j] = 0.0f;

#pragma unroll 2
    for (int s = 0; s < 16; s++) {
        u32 ah[4], al[4];
        ldsm4(aH + (s << 5), ah);
        ldsm4(aL + (s << 5), al);
        uint4 w[NT];
#pragma unroll
        for (int i = 0; i < NT; i++)
            w[i] = Wp[((ntbase + i) << 9) + (s << 5) + lane];
#pragma unroll
        for (int i = 0; i < NT; i++)
            mmab3(c[i], ah, al, w[i].x, w[i].y, w[i].z, w[i].w);
    }

#pragma unroll
    for (int nt = 0; nt < NT; nt++) {
        int col = ((ntbase + nt) << 3) + (t << 1);
        if (PACKOUT) {
            float2 bA = *(const float2*)(biasRows + (m0 + g) * 256 + col);
            float2 bB = *(const float2*)(biasRows + (m0 + 8 + g) * 256 + col);
            u32 hw, lw;
            bsplit(c[nt][0] + bA.x, c[nt][1] + bA.y, hw, lw);
            Ohh[(m0 + g) * LDW + (col >> 1)] = hw;
            Ohl[(m0 + g) * LDW + (col >> 1)] = lw;
            bsplit(c[nt][2] + bB.x, c[nt][3] + bB.y, hw, lw);
            Ohh[(m0 + 8 + g) * LDW + (col >> 1)] = hw;
            Ohl[(m0 + 8 + g) * LDW + (col >> 1)] = lw;
        } else {
            float2 bb = *(const float2*)(biasVec + col);
            *(float2*)(Ofp + (m0 + g) * LDO + col) =
                make_float2(c[nt][0] + bb.x, c[nt][1] + bb.y);
            *(float2*)(Ofp + (m0 + 8 + g) * LDO + col) =
                make_float2(c[nt][2] + bb.x, c[nt][3] + bb.y);
        }
    }
}

// KV (one warp's share): NT n-tiles at local ntl (0..7 within head h).
template<int NT>
__device__ __forceinline__ void gemm_kv_t(
    const u32* Ah, const u32* Al, int h,
    u32* Khh, u32* Khl, u16* Vhh16, u16* Vhl16,
    int mrow, int ntl, bool active, int isV)
{
    if (!active) return;
    const int lane = threadIdx.x & 31;
    const int g = lane >> 2, t = lane & 3;
    const int m0 = mrow << 4;
    const uint4* __restrict__ Wp = g_wr + ((1 + isV) << 14);
    const float* __restrict__ biasRows = g_posb + ((1 + isV) << 14);
    const int lr = lane & 15, hb = lane >> 4;

    const u32 aH = s2u(Ah + (m0 + lr) * LDW + (hb << 2));
    const u32 aL = s2u(Al + (m0 + lr) * LDW + (hb << 2));

    float c[NT][4];
#pragma unroll
    for (int i = 0; i < NT; i++)
#pragma unroll
        for (int j = 0; j < 4; j++) c[i][j] = 0.0f;

#pragma unroll 2
    for (int s = 0; s < 16; s++) {
        u32 ah[4], al[4];
        ldsm4(aH + (s << 5), ah);
        ldsm4(aL + (s << 5), al);
        uint4 w[NT];
#pragma unroll
        for (int i = 0; i < NT; i++)
            w[i] = Wp[(((h << 3) + ntl + i) << 9) + (s << 5) + lane];
#pragma unroll
        for (int i = 0; i < NT; i++)
            mmab3(c[i], ah, al, w[i].x, w[i].y, w[i].z, w[i].w);
    }

#pragma unroll
    for (int nt = 0; nt < NT; nt++) {
        int nl = ((ntl + nt) << 3) + (t << 1);
        int colg = (h << 6) + nl;
        float2 bA = *(const float2*)(biasRows + (m0 + g) * 256 + colg);
        float2 bB = *(const float2*)(biasRows + (m0 + 8 + g) * 256 + colg);
        if (!isV) {
            u32 hw, lww;
            bsplit(c[nt][0] + bA.x, c[nt][1] + bA.y, hw, lww);
            Khh[(m0 + g) * LDWK + (nl >> 1)] = hw;
            Khl[(m0 + g) * LDWK + (nl >> 1)] = lww;
            bsplit(c[nt][2] + bB.x, c[nt][3] + bB.y, hw, lww);
            Khh[(m0 + 8 + g) * LDWK + (nl >> 1)] = hw;
            Khl[(m0 + 8 + g) * LDWK + (nl >> 1)] = lww;
        } else {
            int m = m0 + g;
            u32 hw, lww;
            bsplit(c[nt][0] + bA.x, c[nt][1] + bA.y, hw, lww);
            Vhh16[nl * 72 + m]       = (u16)hw;
            Vhh16[(nl + 1) * 72 + m] = (u16)(hw >> 16);
            Vhl16[nl * 72 + m]       = (u16)lww;
            Vhl16[(nl + 1) * 72 + m] = (u16)(lww >> 16);
            bsplit(c[nt][2] + bB.x, c[nt][3] + bB.y, hw, lww);
            Vhh16[nl * 72 + m + 8]       = (u16)hw;
            Vhh16[(nl + 1) * 72 + m + 8] = (u16)(hw >> 16);
            Vhl16[nl * 72 + m + 8]       = (u16)lww;
            Vhl16[(nl + 1) * 72 + m + 8] = (u16)(lww >> 16);
        }
    }
}

// scores = Q_h @ K_h^T. 32 warps: mrow=wid&3, nc8=wid>>2 (8 cols each).
__device__ __forceinline__ void gemm_scores(
    const u32* Qhh, const u32* Qhl, int h,
    const u32* Khh, const u32* Khl, float* Ss, int mt)
{
    const int wid = threadIdx.x >> 5, lane = threadIdx.x & 31;
    const int mrow = wid & 3, nc8 = wid >> 2;
    if (mrow >= mt || nc8 >= (mt << 1)) return;
    const int g = lane >> 2, t = lane & 3;
    const int m0 = mrow << 4;
    const int lr = lane & 15, hb = lane >> 4;

    const u32 aH = s2u(Qhh + (m0 + lr) * LDW + (h << 5) + (hb << 2));
    const u32 aL = s2u(Qhl + (m0 + lr) * LDW + (h << 5) + (hb << 2));
    const int brow = (nc8 << 3) + (lane & 7);
    const int boff = ((lane >> 3) & 1) << 2;
    const u32 bH = s2u(Khh + brow * LDWK + boff);
    const u32 bL = s2u(Khl + brow * LDWK + boff);

    float c[4];
#pragma unroll
    for (int j = 0; j < 4; j++) c[j] = 0.0f;

#pragma unroll
    for (int s = 0; s < 4; s++) {
        u32 ah[4], al[4], kh[2], kl[2];
        ldsm4(aH + (s << 5), ah);
        ldsm4(aL + (s << 5), al);
        ldsm2(bH + (s << 5), kh);
        ldsm2(bL + (s << 5), kl);
        mmab3(c, ah, al, kh[0], kh[1], kl[0], kl[1]);
    }

    int n0 = (nc8 << 3) + (t << 1);
    *(float2*)(Ss + (m0 + g) * LDF + n0)     = make_float2(c[0], c[1]);
    *(float2*)(Ss + (m0 + 8 + g) * LDF + n0) = make_float2(c[2], c[3]);
}

// ctx_h = P @ V_h -> packed into Q region. 32 warps: mrow=wid&3, nc8=wid>>2.
__device__ __forceinline__ void gemm_pv(
    const u32* Phh, const u32* Phl, const u32* Vhh, const u32* Vhl, int h,
    u32* Qhh, u32* Qhl, int mt)
{
    const int wid = threadIdx.x >> 5, lane = threadIdx.x & 31;
    const int mrow = wid & 3, nc8 = wid >> 2;
    if (mrow >= mt) return;
    const int g = lane >> 2, t = lane & 3;
    const int m0 = mrow << 4;
    const int lr = lane & 15, hb = lane >> 4;

    const u32 aH = s2u(Phh + (m0 + lr) * LDWK + (hb << 2));
    const u32 aL = s2u(Phl + (m0 + lr) * LDWK + (hb << 2));
    const int brow = (nc8 << 3) + (lane & 7);
    const int boff = ((lane >> 3) & 1) << 2;
    const u32 bH = s2u(Vhh + brow * LDWK + boff);
    const u32 bL = s2u(Vhl + brow * LDWK + boff);

    float c[4];
#pragma unroll
    for (int j = 0; j < 4; j++) c[j] = 0.0f;

    for (int s = 0; s < mt; s++) {
        u32 ah[4], al[4], vh[2], vl[2];
        ldsm4(aH + (s << 5), ah);
        ldsm4(aL + (s << 5), al);
        ldsm2(bH + (s << 5), vh);
        ldsm2(bL + (s << 5), vl);
        mmab3(c, ah, al, vh[0], vh[1], vl[0], vl[1]);
    }

    int coll = (nc8 << 3) + (t << 1);
    int wrd = (h << 5) + (coll >> 1);
    u32 hw, lw;
    bsplit(c[0], c[1], hw, lw);
    Qhh[(m0 + g) * LDW + wrd] = hw;
    Qhl[(m0 + g) * LDW + wrd] = lw;
    bsplit(c[2], c[3], hw, lw);
    Qhh[(m0 + 8 + g) * LDW + wrd] = hw;
    Qhl[(m0 + 8 + g) * LDW + wrd] = lw;
}

// ============================================================================
__global__ void __launch_bounds__(1024, 1)
enc_kernel(const float* __restrict__ obstacles, const int* __restrict__ lengths,
           const float* __restrict__ w1, const float* __restrict__ b1,
           const float* __restrict__ bo,
           const float* __restrict__ g1w, const float* __restrict__ g1b,
           const float* __restrict__ g2w, const float* __restrict__ g2b,
           const float* __restrict__ ln_g, const float* __restrict__ ln_b,
           float* __restrict__ out)
{
    extern __shared__ float sm[];
    u32* Thh = (u32*)(sm + OFF_THH);
    u32* Thl = (u32*)(sm + OFF_THL);
    u32* Qhh = (u32*)(sm + OFF_QHH);
    u32* Qhl = (u32*)(sm + OFF_QHL);
    u32* Khh = (u32*)(sm + OFF_KHH);
    u32* Khl = (u32*)(sm + OFF_KHL);
    u32* Phh = (u32*)(sm + OFF_PHH);
    u32* Phl = (u32*)(sm + OFF_PHL);
    u32* Vhh = (u32*)(sm + OFF_VHH);
    u32* Vhl = (u32*)(sm + OFF_VHL);
    u16* Vhh16 = (u16*)Vhh;
    u16* Vhl16 = (u16*)Vhl;
    float* Ss  = sm + OFF_S;
    float* ws  = sm + OFF_WS;     // scratch aliases K/P/V (phase-disjoint)
    float* OutT = sm + OFF_OUT;   // aliases dead T region

    const int b   = blockIdx.x;
    const int tid = threadIdx.x;
    const int len = lengths[b];
    const int mt  = (len + 15) >> 4;          // 1..4 active seq tiles
    const int wid = tid >> 5, lane = tid & 31;

    // ---- stage w1 + obstacles (scratch lives in K/V region: not yet used) ----
    if (tid < 256) {
        *(float4*)(ws + WS_W1 + (tid << 2)) = *(const float4*)(w1 + (tid << 2));
        ws[WS_OBS + tid] = obstacles[b * 256 + tid];
    }
    __syncthreads();

    // ---- phase 1: t = relu(obs @ w1 + b1) -> packed bf16 hi/lo (rows < 16mt) ----
    {
        int cp = tid & 127, q = tid >> 7;     // 8 row-octets
        int c0 = cp << 1;
        float wa0 = ws[WS_W1 + c0],       wa1 = ws[WS_W1 + c0 + 1];
        float wb0 = ws[WS_W1 + 256 + c0], wb1 = ws[WS_W1 + 256 + c0 + 1];
        float wc0 = ws[WS_W1 + 512 + c0], wc1 = ws[WS_W1 + 512 + c0 + 1];
        float wd0 = ws[WS_W1 + 768 + c0], wd1 = ws[WS_W1 + 768 + c0 + 1];
        float bb0 = b1[c0], bb1 = b1[c0 + 1];
        if (q < (mt << 1)) {
            int n0 = q << 3;
#pragma unroll 4
            for (int n = n0; n < n0 + 8; n++) {
                float4 o = *(const float4*)(ws + WS_OBS + (n << 2));
                float v0 = fmaf(o.x, wa0, fmaf(o.y, wb0, fmaf(o.z, wc0, fmaf(o.w, wd0, bb0))));
                float v1 = fmaf(o.x, wa1, fmaf(o.y, wb1, fmaf(o.z, wc1, fmaf(o.w, wd1, bb1))));
                v0 = fmaxf(v0, 0.0f); v1 = fmaxf(v1, 0.0f);
                u32 hw, lw;
                bsplit(v0, v1, hw, lw);
                Thh[n * LDW + cp] = hw;
                Thl[n * LDW + cp] = lw;
            }
        }
    }
    __syncthreads();

    // ---- Q = t @ wq' + posbq (1/8 folded), packed, 32-warp rebalanced ----
    if (mt == 1)
        gemm_big_t<1, true>(Thh, Thl, g_wr, g_posb, nullptr, Qhh, Qhl, nullptr,
                            0, wid, true);
    else if (mt == 2)
        gemm_big_t<2, true>(Thh, Thl, g_wr, g_posb, nullptr, Qhh, Qhl, nullptr,
                            wid & 1, (wid >> 1) << 1, true);
    else
        gemm_big_t<4, true>(Thh, Thl, g_wr, g_posb, nullptr, Qhh, Qhl, nullptr,
                            wid & 3, (wid >> 2) << 2, (wid & 3) < mt);
    __syncthreads();

    // ---- attention heads ----
    const int isV = wid >> 4, lw_ = wid & 15;
#pragma unroll 1
    for (int h = 0; h < 4; h++) {
        if (mt == 1)
            gemm_kv_t<1>(Thh, Thl, h, Khh, Khl, Vhh16, Vhl16,
                         0, lw_, lw_ < 8, isV);
        else if (mt == 2)
            gemm_kv_t<1>(Thh, Thl, h, Khh, Khl, Vhh16, Vhl16,
                         lw_ & 1, lw_ >> 1, true, isV);
        else
            gemm_kv_t<2>(Thh, Thl, h, Khh, Khl, Vhh16, Vhl16,
                         lw_ & 3, (lw_ >> 2) << 1, (lw_ & 3) < mt, isV);
        __syncthreads();

        gemm_scores(Qhh, Qhl, h, Khh, Khl, Ss, mt);
        __syncthreads();

        // masked softmax on rows < 16mt (warp wid owns rows 4wid..+3)
        if (wid < (mt << 2)) {
            bool va = (lane << 1) < len;
            bool vb = ((lane << 1) + 1) < len;
#pragma unroll
            for (int rr = 0; rr < 4; rr++) {
                int r = (wid << 2) + rr;
                float2 x = *(const float2*)(Ss + r * LDF + (lane << 1));
                float m = fmaxf(va ? x.x : -3.4e38f, vb ? x.y : -3.4e38f);
#pragma unroll
                for (int off = 16; off; off >>= 1)
                    m = fmaxf(m, __shfl_xor_sync(0xffffffffu, m, off));
                float e0 = va ? __expf(x.x - m) : 0.0f;
                float e1 = vb ? __expf(x.y - m) : 0.0f;
                float s = e0 + e1;
#pragma unroll
                for (int off = 16; off; off >>= 1)
                    s += __shfl_xor_sync(0xffffffffu, s, off);
                float inv = __frcp_rn(s);
                u32 hw, lw;
                bsplit(e0 * inv, e1 * inv, hw, lw);
                Phh[r * LDWK + lane] = hw;
                Phl[r * LDWK + lane] = lw;
            }
        }
        __syncthreads();

        gemm_pv(Phh, Phl, Vhh, Vhl, h, Qhh, Qhl, mt);
        __syncthreads();
    }

    // ---- out = ctx @ wo + bo -> OutT fp32, rebalanced ----
    if (mt == 1)
        gemm_big_t<1, false>(Qhh, Qhl, g_wr + 3 * 16384, nullptr, bo,
                             nullptr, nullptr, OutT, 0, wid, true);
    else if (mt == 2)
        gemm_big_t<2, false>(Qhh, Qhl, g_wr + 3 * 16384, nullptr, bo,
                             nullptr, nullptr, OutT, wid & 1, (wid >> 1) << 1, true);
    else
        gemm_big_t<4, false>(Qhh, Qhl, g_wr + 3 * 16384, nullptr, bo,
                             nullptr, nullptr, OutT, wid & 3, (wid >> 2) << 2,
                             (wid & 3) < mt);
    __syncthreads();

    // ---- masked mean/max pool: 4-way row-chunk split ----
    {
        int col = tid & 255, q2 = tid >> 8;
        int chunk = (len + 3) >> 2;
        int nb = q2 * chunk; if (nb > len) nb = len;
        int ne = nb + chunk; if (ne > len) ne = len;
        float s = 0.0f, mx = -3.4e38f;
        for (int n = nb; n < ne; n++) {
            float x = OutT[n * LDO + col];
            s += x; mx = fmaxf(mx, x);
        }
        ws[WS_PS + tid] = s;
        ws[WS_PM + tid] = mx;
    }
    __syncthreads();
    if (tid < 256) {
        float s = ws[WS_PS + tid] + ws[WS_PS + 256 + tid]
                + ws[WS_PS + 512 + tid] + ws[WS_PS + 768 + tid];
        float mx = fmaxf(fmaxf(ws[WS_PM + tid], ws[WS_PM + 256 + tid]),
                         fmaxf(ws[WS_PM + 512 + tid], ws[WS_PM + 768 + tid]));
        ws[WS_G + tid]       = s / (float)len;
        ws[WS_G + 256 + tid] = mx;
    }
    __syncthreads();

    // ---- g1: 512 k split 4-way ----
    {
        int col = tid & 255, kq = tid >> 8;
        float acc = 0.0f;
        int kb = kq << 7;
#pragma unroll 8
        for (int k = kb; k < kb + 128; k++)
            acc = fmaf(ws[WS_G + k], g1w[k * 256 + col], acc);
        ws[WS_T1 + tid] = acc;
    }
    __syncthreads();
    if (tid < 256)
        ws[WS_A1 + tid] = fmaxf(ws[WS_T1 + tid] + ws[WS_T1 + 256 + tid]
                              + ws[WS_T1 + 512 + tid] + ws[WS_T1 + 768 + tid]
                              + g1b[tid], 0.0f);
    __syncthreads();

    // ---- g2: 256 k split 4-way ----
    {
        int col = tid & 255, kq = tid >> 8;
        float acc = 0.0f;
        int kb = kq << 6;
#pragma unroll 8
        for (int k = kb; k < kb + 64; k++)
            acc = fmaf(ws[WS_A1 + k], g2w[k * 256 + col], acc);
        ws[WS_T2 + tid] = acc;
    }
    __syncthreads();
    float val = 0.0f;
    if (tid < 256)
        val = ws[WS_T2 + tid] + ws[WS_T2 + 256 + tid]
            + ws[WS_T2 + 512 + tid] + ws[WS_T2 + 768 + tid] + g2b[tid];

    // ---- LayerNorm (first 8 warps carry data) ----
    float s1 = val;
#pragma unroll
    for (int off = 16; off; off >>= 1) s1 += __shfl_xor_sync(0xffffffffu, s1, off);
    if (lane == 0 && wid < 8) ws[WS_RED + wid] = s1;
    __syncthreads();
    float mu = 0.0f;
#pragma unroll
    for (int i = 0; i < 8; i++) mu += ws[WS_RED + i];
    mu *= (1.0f / 256.0f);
    __syncthreads();

    float d0 = val - mu;
    float s2 = d0 * d0;
#pragma unroll
    for (int off = 16; off; off >>= 1) s2 += __shfl_xor_sync(0xffffffffu, s2, off);
    if (lane == 0 && wid < 8) ws[WS_RED + wid] = s2;
    __syncthreads();
    float var = 0.0f;
#pragma unroll
    for (int i = 0; i < 8; i++) var += ws[WS_RED + i];
    var *= (1.0f / 256.0f);

    if (tid < 256)
        out[b * 256 + tid] = d0 * rsqrtf(var + 1e-5f) * ln_g[tid] + ln_b[tid];
}

// ---------------------------------------------------------------------------
extern "C" void kernel_launch(void* const* d_in, const int* in_sizes, int n_in,
                              void* d_out, int out_size)
{
    const float* obstacles = (const float*)d_in[0];
    const int*   lengths   = (const int*)d_in[1];
    const float* w1   = (const float*)d_in[2];
    const float* b1   = (const float*)d_in[3];
    const float* w2   = (const float*)d_in[4];
    const float* b2   = (const float*)d_in[5];
    const float* pos  = (const float*)d_in[6];
    const float* wq   = (const float*)d_in[7];
    const float* bq   = (const float*)d_in[8];
    const float* wk   = (const float*)d_in[9];
    const float* bk   = (const float*)d_in[10];
    const float* wv   = (const float*)d_in[11];
    const float* bv   = (const float*)d_in[12];
    const float* wo   = (const float*)d_in[13];
    const float* bo   = (const float*)d_in[14];
    const float* g1w  = (const float*)d_in[15];
    const float* g1b  = (const float*)d_in[16];
    const float* g2w  = (const float*)d_in[17];
    const float* g2b  = (const float*)d_in[18];
    const float* ln_g = (const float*)d_in[19];
    const float* ln_b = (const float*)d_in[20];
    float* out = (float*)d_out;

    const int B = in_sizes[1];

    fold_k<<<768, 256>>>(w2, wq, wk, wv);
    posfold_k<<<192, 256>>>(pos, b2, wq, wk, wv, bq, bk, bv);
    pack_k<<<256, 256>>>(wo);

    cudaFuncSetAttribute(enc_kernel, cudaFuncAttributeMaxDynamicSharedMemorySize, SMEM_BYTES);
    enc_kernel<<<B, 1024, SMEM_BYTES>>>(
        obstacles, lengths, w1, b1, bo,
        g1w, g1b, g2w, g2b, ln_g, ln_b, out);
}

// round 14
// speedup vs baseline: 1.3373x; 1.0764x over previous
#include <cuda_runtime.h>

// ============================================================================
// AttentionObstacleEncoder via bf16 mma.sync.m16n8k16, 3-term hi/lo split.
// R14 = R13 (1024 thr, length-adaptive tiling) plus:
//   1) g1/g2/LayerNorm moved OUT of enc_kernel into a batched mlp_kernel
//      (32 rows/CTA -> 32x weight amortization; enc writes pooled g to gmem).
//   2) LPT scheduling: CTAs sorted by descending mt via counting sort
//      (atomic scatter; outputs are per-element deterministic).
// ============================================================================

typedef unsigned int u32;
typedef unsigned short u16;

#define LDW  132    // u32-word row stride, packed [64][256] arrays (132%32==4)
#define LDWK 36     // u32-word row stride, packed [64][64] arrays  (36%32==4)
#define LDF  68     // fp32 row stride for scores buffer
#define LDO  260    // fp32 row stride for OutT

// smem word offsets
#define OFF_THH  0        // t hi packed  [64][LDW] = 8448 words
#define OFF_THL  8448
#define OFF_QHH  16896    // Q/ctx hi packed
#define OFF_QHL  25344
#define OFF_KHH  33792    // K_h hi packed [64][LDWK] = 2304 words
#define OFF_KHL  36096
#define OFF_PHH  38400    // P packed
#define OFF_PHL  40704
#define OFF_VHH  43008    // V_h hi packed (u16-addressed, stride 72)
#define OFF_VHL  45312
#define OFF_S    47616    // scores fp32 [64][LDF] = 4352
#define OFF_OUT  0        // OutT fp32 [64][LDO], aliases dead T region
#define OFF_WS   33792    // scratch aliases K/P/V region (phase-disjoint)
#define SMEM_WORDS 51968
#define SMEM_BYTES (SMEM_WORDS * 4)   // 207872

// scratch sub-offsets (floats, relative to OFF_WS)
#define WS_PS   0        // pool partial sums [1024]
#define WS_PM   1024     // pool partial max  [1024]
#define WS_OBS  2048     // obstacles [256]
#define WS_W1   2304     // w1 staged [1024]

#define MLP_SMEM (24832 * 4)   // gs 16384 + a1s 8192 + red 256 floats

// device scratch
__device__ float g_wf[3 * 65536];        // w2@{wq,wk,wv} fp32 (q pre-scaled 1/8)
__device__ float g_posb[3 * 16384];      // [(pos+b2)@wx + bx] per-row bias
__device__ uint4 g_wr[4 * 16384];        // bf16 hi/lo packed: {wq',wk',wv',wo}
__device__ float g_pool[4096 * 512];     // pooled [mean||max] per element
__device__ int   g_cnt[5];
__device__ int   g_cur[5];
__device__ int   g_perm[8192];

__device__ __forceinline__ u32 packbf(float x0, float x1) {
    u32 r; asm("cvt.rn.bf16x2.f32 %0, %2, %1;" : "=r"(r) : "f"(x0), "f"(x1));
    return r;
}
__device__ __forceinline__ void bsplit(float x0, float x1, u32& hw, u32& lw) {
    hw = packbf(x0, x1);
    float h0 = __uint_as_float(hw << 16);
    float h1 = __uint_as_float(hw & 0xffff0000u);
    lw = packbf(x0 - h0, x1 - h1);
}
__device__ __forceinline__ void mmab(float* c, u32 a0, u32 a1, u32 a2, u32 a3,
                                     u32 b0, u32 b1) {
    asm("mma.sync.aligned.m16n8k16.row.col.f32.bf16.bf16.f32 "
        "{%0,%1,%2,%3},{%4,%5,%6,%7},{%8,%9},{%0,%1,%2,%3};"
        : "+f"(c[0]), "+f"(c[1]), "+f"(c[2]), "+f"(c[3])
        : "r"(a0), "r"(a1), "r"(a2), "r"(a3), "r"(b0), "r"(b1));
}
__device__ __forceinline__ void mmab3(float* c, const u32* ah, const u32* al,
                                      u32 bh0, u32 bh1, u32 bl0, u32 bl1) {
    mmab(c, ah[0], ah[1], ah[2], ah[3], bl0, bl1);
    mmab(c, al[0], al[1], al[2], al[3], bh0, bh1);
    mmab(c, ah[0], ah[1], ah[2], ah[3], bh0, bh1);
}
__device__ __forceinline__ u32 s2u(const void* p) {
    return (u32)__cvta_generic_to_shared(p);
}
__device__ __forceinline__ void ldsm4(u32 addr, u32* r) {
    asm volatile("ldmatrix.sync.aligned.m8n8.x4.shared.b16 {%0,%1,%2,%3}, [%4];"
        : "=r"(r[0]), "=r"(r[1]), "=r"(r[2]), "=r"(r[3]) : "r"(addr));
}
__device__ __forceinline__ void ldsm2(u32 addr, u32* r) {
    asm volatile("ldmatrix.sync.aligned.m8n8.x2.shared.b16 {%0,%1}, [%2];"
        : "=r"(r[0]), "=r"(r[1]) : "r"(addr));
}

// ============================================================================
// Prep kernels (per launch, deterministic)
// ============================================================================

__global__ void fold_k(const float* __restrict__ w2, const float* __restrict__ wq,
                       const float* __restrict__ wk, const float* __restrict__ wv)
{
    int m = blockIdx.x >> 8, k = blockIdx.x & 255, c = threadIdx.x;
    const float* wx = (m == 0) ? wq : (m == 1) ? wk : wv;
    float acc = 0.0f;
#pragma unroll 8
    for (int d = 0; d < 256; d++)
        acc = fmaf(__ldg(w2 + k * 256 + d), __ldg(wx + d * 256 + c), acc);
    if (m == 0) acc *= 0.125f;
    g_wf[m * 65536 + k * 256 + c] = acc;
}

__global__ void posfold_k(const float* __restrict__ pos, const float* __restrict__ b2,
                          const float* __restrict__ wq, const float* __restrict__ wk,
                          const float* __restrict__ wv, const float* __restrict__ bq,
                          const float* __restrict__ bk, const float* __restrict__ bv)
{
    int m = blockIdx.x >> 6, n = blockIdx.x & 63, c = threadIdx.x;
    const float* wx = (m == 0) ? wq : (m == 1) ? wk : wv;
    const float* bx = (m == 0) ? bq : (m == 1) ? bk : bv;
    float acc = __ldg(bx + c);
#pragma unroll 8
    for (int d = 0; d < 256; d++)
        acc = fmaf(__ldg(pos + n * 256 + d) + __ldg(b2 + d), __ldg(wx + d * 256 + c), acc);
    if (m == 0) acc *= 0.125f;
    g_posb[m * 16384 + n * 256 + c] = acc;
}

__global__ void pack_k(const float* __restrict__ wo)
{
    int idx = blockIdx.x * 256 + threadIdx.x;   // 0 .. 65535
    int m = idx >> 14;
    int u = idx & 16383;
    int ntile = u >> 9;
    int s = (u >> 5) & 15;
    int lane = u & 31;
    int g = lane >> 2, t = lane & 3;
    int n = ntile * 8 + g;
    int k0 = s * 16 + t * 2;
    const float* W = (m < 3) ? (g_wf + m * 65536) : wo;
    float f0 = W[k0 * 256 + n];
    float f1 = W[(k0 + 1) * 256 + n];
    float f2 = W[(k0 + 8) * 256 + n];
    float f3 = W[(k0 + 9) * 256 + n];
    uint4 r;
    bsplit(f0, f1, r.x, r.z);
    bsplit(f2, f3, r.y, r.w);
    g_wr[idx] = r;
}

// ---- LPT sort by descending mt (counting sort; perm order nondeterministic
// but per-element outputs identical) ----
__global__ void sort0_k() {
    if (threadIdx.x < 5) { g_cnt[threadIdx.x] = 0; g_cur[threadIdx.x] = 0; }
}
__global__ void sort1_k(const int* __restrict__ lengths, int B) {
    int i = blockIdx.x * 256 + threadIdx.x;
    if (i < B) atomicAdd(&g_cnt[(lengths[i] + 15) >> 4], 1);
}
__global__ void sort2_k() {
    g_cur[4] = 0;
    g_cur[3] = g_cnt[4];
    g_cur[2] = g_cnt[4] + g_cnt[3];
    g_cur[1] = g_cnt[4] + g_cnt[3] + g_cnt[2];
}
__global__ void sort3_k(const int* __restrict__ lengths, int B) {
    int i = blockIdx.x * 256 + threadIdx.x;
    if (i < B) {
        int mt = (lengths[i] + 15) >> 4;
        int idx = atomicAdd(&g_cur[mt], 1);
        g_perm[idx] = i;
    }
}

// ============================================================================
// Device GEMM pieces
// ============================================================================

template<int NT, bool PACKOUT>
__device__ __forceinline__ void gemm_big_t(
    const u32* Ah, const u32* Al, const uint4* __restrict__ Wp,
    const float* __restrict__ biasRows, const float* __restrict__ biasVec,
    u32* Ohh, u32* Ohl, float* Ofp, int mrow, int ntbase, bool active)
{
    if (!active) return;
    const int lane = threadIdx.x & 31;
    const int g = lane >> 2, t = lane & 3;
    const int m0 = mrow << 4;
    const int lr = lane & 15, hb = lane >> 4;

    const u32 aH = s2u(Ah + (m0 + lr) * LDW + (hb << 2));
    const u32 aL = s2u(Al + (m0 + lr) * LDW + (hb << 2));

    float c[NT][4];
#pragma unroll
    for (int i = 0; i < NT; i++)
#pragma unroll
        for (int j = 0; j < 4; j++) c[i][j] = 0.0f;

#pragma unroll 2
    for (int s = 0; s < 16; s++) {
        u32 ah[4], al[4];
        ldsm4(aH + (s << 5), ah);
        ldsm4(aL + (s << 5), al);
        uint4 w[NT];
#pragma unroll
        for (int i = 0; i < NT; i++)
            w[i] = Wp[((ntbase + i) << 9) + (s << 5) + lane];
#pragma unroll
        for (int i = 0; i < NT; i++)
            mmab3(c[i], ah, al, w[i].x, w[i].y, w[i].z, w[i].w);
    }

#pragma unroll
    for (int nt = 0; nt < NT; nt++) {
        int col = ((ntbase + nt) << 3) + (t << 1);
        if (PACKOUT) {
            float2 bA = *(const float2*)(biasRows + (m0 + g) * 256 + col);
            float2 bB = *(const float2*)(biasRows + (m0 + 8 + g) * 256 + col);
            u32 hw, lw;
            bsplit(c[nt][0] + bA.x, c[nt][1] + bA.y, hw, lw);
            Ohh[(m0 + g) * LDW + (col >> 1)] = hw;
            Ohl[(m0 + g) * LDW + (col >> 1)] = lw;
            bsplit(c[nt][2] + bB.x, c[nt][3] + bB.y, hw, lw);
            Ohh[(m0 + 8 + g) * LDW + (col >> 1)] = hw;
            Ohl[(m0 + 8 + g) * LDW + (col >> 1)] = lw;
        } else {
            float2 bb = *(const float2*)(biasVec + col);
            *(float2*)(Ofp + (m0 + g) * LDO + col) =
                make_float2(c[nt][0] + bb.x, c[nt][1] + bb.y);
            *(float2*)(Ofp + (m0 + 8 + g) * LDO + col) =
                make_float2(c[nt][2] + bb.x, c[nt][3] + bb.y);
        }
    }
}

template<int NT>
__device__ __forceinline__ void gemm_kv_t(
    const u32* Ah, const u32* Al, int h,
    u32* Khh, u32* Khl, u16* Vhh16, u16* Vhl16,
    int mrow, int ntl, bool active, int isV)
{
    if (!active) return;
    const int lane = threadIdx.x & 31;
    const int g = lane >> 2, t = lane & 3;
    const int m0 = mrow << 4;
    const uint4* __restrict__ Wp = g_wr + ((1 + isV) << 14);
    const float* __restrict__ biasRows = g_posb + ((1 + isV) << 14);
    const int lr = lane & 15, hb = lane >> 4;

    const u32 aH = s2u(Ah + (m0 + lr) * LDW + (hb << 2));
    const u32 aL = s2u(Al + (m0 + lr) * LDW + (hb << 2));

    float c[NT][4];
#pragma unroll
    for (int i = 0; i < NT; i++)
#pragma unroll
        for (int j = 0; j < 4; j++) c[i][j] = 0.0f;

#pragma unroll 2
    for (int s = 0; s < 16; s++) {
        u32 ah[4], al[4];
        ldsm4(aH + (s << 5), ah);
        ldsm4(aL + (s << 5), al);
        uint4 w[NT];
#pragma unroll
        for (int i = 0; i < NT; i++)
            w[i] = Wp[(((h << 3) + ntl + i) << 9) + (s << 5) + lane];
#pragma unroll
        for (int i = 0; i < NT; i++)
            mmab3(c[i], ah, al, w[i].x, w[i].y, w[i].z, w[i].w);
    }

#pragma unroll
    for (int nt = 0; nt < NT; nt++) {
        int nl = ((ntl + nt) << 3) + (t << 1);
        int colg = (h << 6) + nl;
        float2 bA = *(const float2*)(biasRows + (m0 + g) * 256 + colg);
        float2 bB = *(const float2*)(biasRows + (m0 + 8 + g) * 256 + colg);
        if (!isV) {
            u32 hw, lww;
            bsplit(c[nt][0] + bA.x, c[nt][1] + bA.y, hw, lww);
            Khh[(m0 + g) * LDWK + (nl >> 1)] = hw;
            Khl[(m0 + g) * LDWK + (nl >> 1)] = lww;
            bsplit(c[nt][2] + bB.x, c[nt][3] + bB.y, hw, lww);
            Khh[(m0 + 8 + g) * LDWK + (nl >> 1)] = hw;
            Khl[(m0 + 8 + g) * LDWK + (nl >> 1)] = lww;
        } else {
            int m = m0 + g;
            u32 hw, lww;
            bsplit(c[nt][0] + bA.x, c[nt][1] + bA.y, hw, lww);
            Vhh16[nl * 72 + m]       = (u16)hw;
            Vhh16[(nl + 1) * 72 + m] = (u16)(hw >> 16);
            Vhl16[nl * 72 + m]       = (u16)lww;
            Vhl16[(nl + 1) * 72 + m] = (u16)(lww >> 16);
            bsplit(c[nt][2] + bB.x, c[nt][3] + bB.y, hw, lww);
            Vhh16[nl * 72 + m + 8]       = (u16)hw;
            Vhh16[(nl + 1) * 72 + m + 8] = (u16)(hw >> 16);
            Vhl16[nl * 72 + m + 8]       = (u16)lww;
            Vhl16[(nl + 1) * 72 + m + 8] = (u16)(lww >> 16);
        }
    }
}

__device__ __forceinline__ void gemm_scores(
    const u32* Qhh, const u32* Qhl, int h,
    const u32* Khh, const u32* Khl, float* Ss, int mt)
{
    const int wid = threadIdx.x >> 5, lane = threadIdx.x & 31;
    const int mrow = wid & 3, nc8 = wid >> 2;
    if (mrow >= mt || nc8 >= (mt << 1)) return;
    const int g = lane >> 2, t = lane & 3;
    const int m0 = mrow << 4;
    const int lr = lane & 15, hb = lane >> 4;

    const u32 aH = s2u(Qhh + (m0 + lr) * LDW + (h << 5) + (hb << 2));
    const u32 aL = s2u(Qhl + (m0 + lr) * LDW + (h << 5) + (hb << 2));
    const int brow = (nc8 << 3) + (lane & 7);
    const int boff = ((lane >> 3) & 1) << 2;
    const u32 bH = s2u(Khh + brow * LDWK + boff);
    const u32 bL = s2u(Khl + brow * LDWK + boff);

    float c[4];
#pragma unroll
    for (int j = 0; j < 4; j++) c[j] = 0.0f;

#pragma unroll
    for (int s = 0; s < 4; s++) {
        u32 ah[4], al[4], kh[2], kl[2];
        ldsm4(aH + (s << 5), ah);
        ldsm4(aL + (s << 5), al);
        ldsm2(bH + (s << 5), kh);
        ldsm2(bL + (s << 5), kl);
        mmab3(c, ah, al, kh[0], kh[1], kl[0], kl[1]);
    }

    int n0 = (nc8 << 3) + (t << 1);
    *(float2*)(Ss + (m0 + g) * LDF + n0)     = make_float2(c[0], c[1]);
    *(float2*)(Ss + (m0 + 8 + g) * LDF + n0) = make_float2(c[2], c[3]);
}

__device__ __forceinline__ void gemm_pv(
    const u32* Phh, const u32* Phl, const u32* Vhh, const u32* Vhl, int h,
    u32* Qhh, u32* Qhl, int mt)
{
    const int wid = threadIdx.x >> 5, lane = threadIdx.x & 31;
    const int mrow = wid & 3, nc8 = wid >> 2;
    if (mrow >= mt) return;
    const int g = lane >> 2, t = lane & 3;
    const int m0 = mrow << 4;
    const int lr = lane & 15, hb = lane >> 4;

    const u32 aH = s2u(Phh + (m0 + lr) * LDWK + (hb << 2));
    const u32 aL = s2u(Phl + (m0 + lr) * LDWK + (hb << 2));
    const int brow = (nc8 << 3) + (lane & 7);
    const int boff = ((lane >> 3) & 1) << 2;
    const u32 bH = s2u(Vhh + brow * LDWK + boff);
    const u32 bL = s2u(Vhl + brow * LDWK + boff);

    float c[4];
#pragma unroll
    for (int j = 0; j < 4; j++) c[j] = 0.0f;

    for (int s = 0; s < mt; s++) {
        u32 ah[4], al[4], vh[2], vl[2];
        ldsm4(aH + (s << 5), ah);
        ldsm4(aL + (s << 5), al);
        ldsm2(bH + (s << 5), vh);
        ldsm2(bL + (s << 5), vl);
        mmab3(c, ah, al, vh[0], vh[1], vl[0], vl[1]);
    }

    int coll = (nc8 << 3) + (t << 1);
    int wrd = (h << 5) + (coll >> 1);
    u32 hw, lw;
    bsplit(c[0], c[1], hw, lw);
    Qhh[(m0 + g) * LDW + wrd] = hw;
    Qhl[(m0 + g) * LDW + wrd] = lw;
    bsplit(c[2], c[3], hw, lw);
    Qhh[(m0 + 8 + g) * LDW + wrd] = hw;
    Qhl[(m0 + 8 + g) * LDW + wrd] = lw;
}

// ============================================================================
__global__ void __launch_bounds__(1024, 1)
enc_kernel(const float* __restrict__ obstacles, const int* __restrict__ lengths,
           const float* __restrict__ w1, const float* __restrict__ b1,
           const float* __restrict__ bo)
{
    extern __shared__ float sm[];
    u32* Thh = (u32*)(sm + OFF_THH);
    u32* Thl = (u32*)(sm + OFF_THL);
    u32* Qhh = (u32*)(sm + OFF_QHH);
    u32* Qhl = (u32*)(sm + OFF_QHL);
    u32* Khh = (u32*)(sm + OFF_KHH);
    u32* Khl = (u32*)(sm + OFF_KHL);
    u32* Phh = (u32*)(sm + OFF_PHH);
    u32* Phl = (u32*)(sm + OFF_PHL);
    u32* Vhh = (u32*)(sm + OFF_VHH);
    u32* Vhl = (u32*)(sm + OFF_VHL);
    u16* Vhh16 = (u16*)Vhh;
    u16* Vhl16 = (u16*)Vhl;
    float* Ss  = sm + OFF_S;
    float* ws  = sm + OFF_WS;     // scratch aliases K/P/V (phase-disjoint)
    float* OutT = sm + OFF_OUT;   // aliases dead T region

    const int b   = g_perm[blockIdx.x];       // LPT order
    const int tid = threadIdx.x;
    const int len = lengths[b];
    const int mt  = (len + 15) >> 4;
    const int wid = tid >> 5, lane = tid & 31;

    // ---- stage w1 + obstacles ----
    if (tid < 256) {
        *(float4*)(ws + WS_W1 + (tid << 2)) = *(const float4*)(w1 + (tid << 2));
        ws[WS_OBS + tid] = obstacles[b * 256 + tid];
    }
    __syncthreads();

    // ---- phase 1: t = relu(obs @ w1 + b1) -> packed bf16 hi/lo (rows < 16mt) ----
    {
        int cp = tid & 127, q = tid >> 7;
        int c0 = cp << 1;
        float wa0 = ws[WS_W1 + c0],       wa1 = ws[WS_W1 + c0 + 1];
        float wb0 = ws[WS_W1 + 256 + c0], wb1 = ws[WS_W1 + 256 + c0 + 1];
        float wc0 = ws[WS_W1 + 512 + c0], wc1 = ws[WS_W1 + 512 + c0 + 1];
        float wd0 = ws[WS_W1 + 768 + c0], wd1 = ws[WS_W1 + 768 + c0 + 1];
        float bb0 = b1[c0], bb1 = b1[c0 + 1];
        if (q < (mt << 1)) {
            int n0 = q << 3;
#pragma unroll 4
            for (int n = n0; n < n0 + 8; n++) {
                float4 o = *(const float4*)(ws + WS_OBS + (n << 2));
                float v0 = fmaf(o.x, wa0, fmaf(o.y, wb0, fmaf(o.z, wc0, fmaf(o.w, wd0, bb0))));
                float v1 = fmaf(o.x, wa1, fmaf(o.y, wb1, fmaf(o.z, wc1, fmaf(o.w, wd1, bb1))));
                v0 = fmaxf(v0, 0.0f); v1 = fmaxf(v1, 0.0f);
                u32 hw, lw;
                bsplit(v0, v1, hw, lw);
                Thh[n * LDW + cp] = hw;
                Thl[n * LDW + cp] = lw;
            }
        }
    }
    __syncthreads();

    // ---- Q = t @ wq' + posbq (1/8 folded), packed, 32-warp rebalanced ----
    if (mt == 1)
        gemm_big_t<1, true>(Thh, Thl, g_wr, g_posb, nullptr, Qhh, Qhl, nullptr,
                            0, wid, true);
    else if (mt == 2)
        gemm_big_t<2, true>(Thh, Thl, g_wr, g_posb, nullptr, Qhh, Qhl, nullptr,
                            wid & 1, (wid >> 1) << 1, true);
    else
        gemm_big_t<4, true>(Thh, Thl, g_wr, g_posb, nullptr, Qhh, Qhl, nullptr,
                            wid & 3, (wid >> 2) << 2, (wid & 3) < mt);
    __syncthreads();

    // ---- attention heads ----
    const int isV = wid >> 4, lw_ = wid & 15;
#pragma unroll 1
    for (int h = 0; h < 4; h++) {
        if (mt == 1)
            gemm_kv_t<1>(Thh, Thl, h, Khh, Khl, Vhh16, Vhl16,
                         0, lw_, lw_ < 8, isV);
        else if (mt == 2)
            gemm_kv_t<1>(Thh, Thl, h, Khh, Khl, Vhh16, Vhl16,
                         lw_ & 1, lw_ >> 1, true, isV);
        else
            gemm_kv_t<2>(Thh, Thl, h, Khh, Khl, Vhh16, Vhl16,
                         lw_ & 3, (lw_ >> 2) << 1, (lw_ & 3) < mt, isV);
        __syncthreads();

        gemm_scores(Qhh, Qhl, h, Khh, Khl, Ss, mt);
        __syncthreads();

        // masked softmax on rows < 16mt
        if (wid < (mt << 2)) {
            bool va = (lane << 1) < len;
            bool vb = ((lane << 1) + 1) < len;
#pragma unroll
            for (int rr = 0; rr < 4; rr++) {
                int r = (wid << 2) + rr;
                float2 x = *(const float2*)(Ss + r * LDF + (lane << 1));
                float m = fmaxf(va ? x.x : -3.4e38f, vb ? x.y : -3.4e38f);
#pragma unroll
                for (int off = 16; off; off >>= 1)
                    m = fmaxf(m, __shfl_xor_sync(0xffffffffu, m, off));
                float e0 = va ? __expf(x.x - m) : 0.0f;
                float e1 = vb ? __expf(x.y - m) : 0.0f;
                float s = e0 + e1;
#pragma unroll
                for (int off = 16; off; off >>= 1)
                    s += __shfl_xor_sync(0xffffffffu, s, off);
                float inv = __frcp_rn(s);
                u32 hw, lw;
                bsplit(e0 * inv, e1 * inv, hw, lw);
                Phh[r * LDWK + lane] = hw;
                Phl[r * LDWK + lane] = lw;
            }
        }
        __syncthreads();

        gemm_pv(Phh, Phl, Vhh, Vhl, h, Qhh, Qhl, mt);
        __syncthreads();
    }

    // ---- out = ctx @ wo + bo -> OutT fp32 ----
    if (mt == 1)
        gemm_big_t<1, false>(Qhh, Qhl, g_wr + 3 * 16384, nullptr, bo,
                             nullptr, nullptr, OutT, 0, wid, true);
    else if (mt == 2)
        gemm_big_t<2, false>(Qhh, Qhl, g_wr + 3 * 16384, nullptr, bo,
                             nullptr, nullptr, OutT, wid & 1, (wid >> 1) << 1, true);
    else
        gemm_big_t<4, false>(Qhh, Qhl, g_wr + 3 * 16384, nullptr, bo,
                             nullptr, nullptr, OutT, wid & 3, (wid >> 2) << 2,
                             (wid & 3) < mt);
    __syncthreads();

    // ---- masked mean/max pool -> g_pool[b] ----
    {
        int col = tid & 255, q2 = tid >> 8;
        int chunk = (len + 3) >> 2;
        int nb = q2 * chunk; if (nb > len) nb = len;
        int ne = nb + chunk; if (ne > len) ne = len;
        float s = 0.0f, mx = -3.4e38f;
        for (int n = nb; n < ne; n++) {
            float x = OutT[n * LDO + col];
            s += x; mx = fmaxf(mx, x);
        }
        ws[WS_PS + tid] = s;
        ws[WS_PM + tid] = mx;
    }
    __syncthreads();
    if (tid < 256) {
        float s = ws[WS_PS + tid] + ws[WS_PS + 256 + tid]
                + ws[WS_PS + 512 + tid] + ws[WS_PS + 768 + tid];
        float mx = fmaxf(fmaxf(ws[WS_PM + tid], ws[WS_PM + 256 + tid]),
                         fmaxf(ws[WS_PM + 512 + tid], ws[WS_PM + 768 + tid]));
        g_pool[b * 512 + tid]       = s / (float)len;
        g_pool[b * 512 + 256 + tid] = mx;
    }
}

// ============================================================================
// Batched MLP + LayerNorm: 32 rows per CTA (32x weight amortization).
// ============================================================================
__global__ void __launch_bounds__(256, 1)
mlp_kernel(const float* __restrict__ g1w, const float* __restrict__ g1b,
           const float* __restrict__ g2w, const float* __restrict__ g2b,
           const float* __restrict__ ln_g, const float* __restrict__ ln_b,
           float* __restrict__ out, int B)
{
    extern __shared__ float ms[];
    float* gs  = ms;            // [32][512], later reused as v[32][256]
    float* a1s = ms + 16384;    // [32][256]
    float* red = ms + 24576;    // [32][8]
    const int tid = threadIdx.x;
    const int r0 = blockIdx.x << 5;

    // stage 32 pooled rows
    for (int i = tid; i < 4096; i += 256) {       // 4096 float4
        float4 v = make_float4(0.f, 0.f, 0.f, 0.f);
        if (r0 + (i >> 7) < B)
            v = ((const float4*)g_pool)[r0 * 128 + i];
        ((float4*)gs)[i] = v;
    }
    __syncthreads();

    // g1: each thread owns one output column for all 32 rows
    float acc[32];
#pragma unroll
    for (int r = 0; r < 32; r++) acc[r] = 0.0f;
#pragma unroll 1
    for (int k4 = 0; k4 < 512; k4 += 4) {
        float w0 = g1w[k4 * 256 + tid];
        float w1 = g1w[(k4 + 1) * 256 + tid];
        float w2 = g1w[(k4 + 2) * 256 + tid];
        float w3 = g1w[(k4 + 3) * 256 + tid];
#pragma unroll
        for (int r = 0; r < 32; r++) {
            float4 g4 = *(const float4*)(gs + (r << 9) + k4);
            acc[r] = fmaf(g4.w, w3, fmaf(g4.z, w2, fmaf(g4.y, w1, fmaf(g4.x, w0, acc[r]))));
        }
    }
    {
        float bb = g1b[tid];
#pragma unroll
        for (int r = 0; r < 32; r++)
            a1s[(r << 8) + tid] = fmaxf(acc[r] + bb, 0.0f);
    }
    __syncthreads();

    // g2
#pragma unroll
    for (int r = 0; r < 32; r++) acc[r] = 0.0f;
#pragma unroll 1
    for (int k4 = 0; k4 < 256; k4 += 4) {
        float w0 = g2w[k4 * 256 + tid];
        float w1 = g2w[(k4 + 1) * 256 + tid];
        float w2 = g2w[(k4 + 2) * 256 + tid];
        float w3 = g2w[(k4 + 3) * 256 + tid];
#pragma unroll
        for (int r = 0; r < 32; r++) {
            float4 a4 = *(const float4*)(a1s + (r << 8) + k4);
            acc[r] = fmaf(a4.w, w3, fmaf(a4.z, w2, fmaf(a4.y, w1, fmaf(a4.x, w0, acc[r]))));
        }
    }
    __syncthreads();   // gs reads are done; safe to overwrite as v
    {
        float bb = g2b[tid];
#pragma unroll
        for (int r = 0; r < 32; r++)
            gs[(r << 8) + tid] = acc[r] + bb;     // v[32][256]
    }
    __syncthreads();

    // LayerNorm per row: 8 threads/row, 32 cols each
    const int r = tid >> 3, sub = tid & 7;
    const int c0 = sub << 5;
    float s = 0.0f;
#pragma unroll 8
    for (int c = c0; c < c0 + 32; c++) s += gs[(r << 8) + c];
    red[(r << 3) + sub] = s;
    __syncthreads();
    float mu = 0.0f;
#pragma unroll
    for (int i = 0; i < 8; i++) mu += red[(r << 3) + i];
    mu *= (1.0f / 256.0f);
    __syncthreads();
    float s2 = 0.0f;
#pragma unroll 8
    for (int c = c0; c < c0 + 32; c++) {
        float d = gs[(r << 8) + c] - mu;
        s2 += d * d;
    }
    red[(r << 3) + sub] = s2;
    __syncthreads();
    float var = 0.0f;
#pragma unroll
    for (int i = 0; i < 8; i++) var += red[(r << 3) + i];
    var *= (1.0f / 256.0f);
    float rstd = rsqrtf(var + 1e-5f);
    if (r0 + r < B) {
#pragma unroll 8
        for (int c = c0; c < c0 + 32; c++)
            out[(r0 + r) * 256 + c] =
                (gs[(r << 8) + c] - mu) * rstd * ln_g[c] + ln_b[c];
    }
}

// ---------------------------------------------------------------------------
extern "C" void kernel_launch(void* const* d_in, const int* in_sizes, int n_in,
                              void* d_out, int out_size)
{
    const float* obstacles = (const float*)d_in[0];
    const int*   lengths   = (const int*)d_in[1];
    const float* w1   = (const float*)d_in[2];
    const float* b1   = (const float*)d_in[3];
    const float* w2   = (const float*)d_in[4];
    const float* b2   = (const float*)d_in[5];
    const float* pos  = (const float*)d_in[6];
    const float* wq   = (const float*)d_in[7];
    const float* bq   = (const float*)d_in[8];
    const float* wk   = (const float*)d_in[9];
    const float* bk   = (const float*)d_in[10];
    const float* wv   = (const float*)d_in[11];
    const float* bv   = (const float*)d_in[12];
    const float* wo   = (const float*)d_in[13];
    const float* bo   = (const float*)d_in[14];
    const float* g1w  = (const float*)d_in[15];
    const float* g1b  = (const float*)d_in[16];
    const float* g2w  = (const float*)d_in[17];
    const float* g2b  = (const float*)d_in[18];
    const float* ln_g = (const float*)d_in[19];
    const float* ln_b = (const float*)d_in[20];
    float* out = (float*)d_out;

    const int B = in_sizes[1];
    const int gB = (B + 255) / 256;

    sort0_k<<<1, 32>>>();
    sort1_k<<<gB, 256>>>(lengths, B);
    sort2_k<<<1, 1>>>();
    sort3_k<<<gB, 256>>>(lengths, B);

    fold_k<<<768, 256>>>(w2, wq, wk, wv);
    posfold_k<<<192, 256>>>(pos, b2, wq, wk, wv, bq, bk, bv);
    pack_k<<<256, 256>>>(wo);

    cudaFuncSetAttribute(enc_kernel, cudaFuncAttributeMaxDynamicSharedMemorySize, SMEM_BYTES);
    enc_kernel<<<B, 1024, SMEM_BYTES>>>(obstacles, lengths, w1, b1, bo);

    cudaFuncSetAttribute(mlp_kernel, cudaFuncAttributeMaxDynamicSharedMemorySize, MLP_SMEM);
    mlp_kernel<<<(B + 31) / 32, 256, MLP_SMEM>>>(g1w, g1b, g2w, g2b, ln_g, ln_b, out, B);
}

// round 15
// speedup vs baseline: 1.4272x; 1.0672x over previous
#include <cuda_runtime.h>

// ============================================================================
// AttentionObstacleEncoder via bf16 mma.sync.m16n8k16, 3-term hi/lo split.
// R15: batch-element PACKING. Small sequences share one CTA's 64-row frame:
//   mode0: single element (mt 3..4), rows [0,16*mt)
//   mode1: pair of mt<=2 elements, rows 0/32 (rps=32)
//   mode2: quad of mt<=1 elements, rows 0/16/32/48 (rps=16)
// Attention stays exact via block-diagonal masking: scores only for
// same-segment tiles; softmax masks keys to [c0,c0+len) and zeros elsewhere;
// pos-bias row = super-row & (rps-1); padded slots zero-filled (finite).
// CTA count drops 4096 -> ~2816 at equal FLOPs => ~31% less weight traffic.
// CTA composition derives from counting-sort offsets (deterministic outputs).
// Plus R14's batched MLP kernel and LPT ordering.
// ============================================================================

typedef unsigned int u32;
typedef unsigned short u16;

#define LDW  132
#define LDWK 36
#define LDF  68
#define LDO  260

#define OFF_THH  0
#define OFF_THL  8448
#define OFF_QHH  16896
#define OFF_QHL  25344
#define OFF_KHH  33792
#define OFF_KHL  36096
#define OFF_PHH  38400
#define OFF_PHL  40704
#define OFF_VHH  43008
#define OFF_VHL  45312
#define OFF_S    47616
#define OFF_OUT  0
#define OFF_WS   33792
#define SMEM_WORDS 51968
#define SMEM_BYTES (SMEM_WORDS * 4)

#define WS_PS   0
#define WS_PM   1024
#define WS_OBS  2048
#define WS_W1   2304

#define MLP_SMEM (24832 * 4)

__device__ float g_wf[3 * 65536];
__device__ float g_posb[3 * 16384];
__device__ uint4 g_wr[4 * 16384];
__device__ float g_pool[4096 * 512];
__device__ int   g_cnt[5];
__device__ int   g_cur[5];
__device__ int   g_perm[8192];

__device__ __forceinline__ u32 packbf(float x0, float x1) {
    u32 r; asm("cvt.rn.bf16x2.f32 %0, %2, %1;" : "=r"(r) : "f"(x0), "f"(x1));
    return r;
}
__device__ __forceinline__ void bsplit(float x0, float x1, u32& hw, u32& lw) {
    hw = packbf(x0, x1);
    float h0 = __uint_as_float(hw << 16);
    float h1 = __uint_as_float(hw & 0xffff0000u);
    lw = packbf(x0 - h0, x1 - h1);
}
__device__ __forceinline__ void mmab(float* c, u32 a0, u32 a1, u32 a2, u32 a3,
                                     u32 b0, u32 b1) {
    asm("mma.sync.aligned.m16n8k16.row.col.f32.bf16.bf16.f32 "
        "{%0,%1,%2,%3},{%4,%5,%6,%7},{%8,%9},{%0,%1,%2,%3};"
        : "+f"(c[0]), "+f"(c[1]), "+f"(c[2]), "+f"(c[3])
        : "r"(a0), "r"(a1), "r"(a2), "r"(a3), "r"(b0), "r"(b1));
}
__device__ __forceinline__ void mmab3(float* c, const u32* ah, const u32* al,
                                      u32 bh0, u32 bh1, u32 bl0, u32 bl1) {
    mmab(c, ah[0], ah[1], ah[2], ah[3], bl0, bl1);
    mmab(c, al[0], al[1], al[2], al[3], bh0, bh1);
    mmab(c, ah[0], ah[1], ah[2], ah[3], bh0, bh1);
}
__device__ __forceinline__ u32 s2u(const void* p) {
    return (u32)__cvta_generic_to_shared(p);
}
__device__ __forceinline__ void ldsm4(u32 addr, u32* r) {
    asm volatile("ldmatrix.sync.aligned.m8n8.x4.shared.b16 {%0,%1,%2,%3}, [%4];"
        : "=r"(r[0]), "=r"(r[1]), "=r"(r[2]), "=r"(r[3]) : "r"(addr));
}
__device__ __forceinline__ void ldsm2(u32 addr, u32* r) {
    asm volatile("ldmatrix.sync.aligned.m8n8.x2.shared.b16 {%0,%1}, [%2];"
        : "=r"(r[0]), "=r"(r[1]) : "r"(addr));
}

// ============================================================================
// Prep kernels
// ============================================================================

__global__ void fold_k(const float* __restrict__ w2, const float* __restrict__ wq,
                       const float* __restrict__ wk, const float* __restrict__ wv)
{
    int m = blockIdx.x >> 8, k = blockIdx.x & 255, c = threadIdx.x;
    const float* wx = (m == 0) ? wq : (m == 1) ? wk : wv;
    float acc = 0.0f;
#pragma unroll 8
    for (int d = 0; d < 256; d++)
        acc = fmaf(__ldg(w2 + k * 256 + d), __ldg(wx + d * 256 + c), acc);
    if (m == 0) acc *= 0.125f;
    g_wf[m * 65536 + k * 256 + c] = acc;
}

__global__ void posfold_k(const float* __restrict__ pos, const float* __restrict__ b2,
                          const float* __restrict__ wq, const float* __restrict__ wk,
                          const float* __restrict__ wv, const float* __restrict__ bq,
                          const float* __restrict__ bk, const float* __restrict__ bv)
{
    int m = blockIdx.x >> 6, n = blockIdx.x & 63, c = threadIdx.x;
    const float* wx = (m == 0) ? wq : (m == 1) ? wk : wv;
    const float* bx = (m == 0) ? bq : (m == 1) ? bk : bv;
    float acc = __ldg(bx + c);
#pragma unroll 8
    for (int d = 0; d < 256; d++)
        acc = fmaf(__ldg(pos + n * 256 + d) + __ldg(b2 + d), __ldg(wx + d * 256 + c), acc);
    if (m == 0) acc *= 0.125f;
    g_posb[m * 16384 + n * 256 + c] = acc;
}

__global__ void pack_k(const float* __restrict__ wo)
{
    int idx = blockIdx.x * 256 + threadIdx.x;
    int m = idx >> 14;
    int u = idx & 16383;
    int ntile = u >> 9;
    int s = (u >> 5) & 15;
    int lane = u & 31;
    int g = lane >> 2, t = lane & 3;
    int n = ntile * 8 + g;
    int k0 = s * 16 + t * 2;
    const float* W = (m < 3) ? (g_wf + m * 65536) : wo;
    float f0 = W[k0 * 256 + n];
    float f1 = W[(k0 + 1) * 256 + n];
    float f2 = W[(k0 + 8) * 256 + n];
    float f3 = W[(k0 + 9) * 256 + n];
    uint4 r;
    bsplit(f0, f1, r.x, r.z);
    bsplit(f2, f3, r.y, r.w);
    g_wr[idx] = r;
}

// counting sort by descending mt
__global__ void sort0_k() {
    if (threadIdx.x < 5) { g_cnt[threadIdx.x] = 0; g_cur[threadIdx.x] = 0; }
}
__global__ void sort1_k(const int* __restrict__ lengths, int B) {
    int i = blockIdx.x * 256 + threadIdx.x;
    if (i < B) atomicAdd(&g_cnt[(lengths[i] + 15) >> 4], 1);
}
__global__ void sort2_k() {
    g_cur[4] = 0;
    g_cur[3] = g_cnt[4];
    g_cur[2] = g_cnt[4] + g_cnt[3];
    g_cur[1] = g_cnt[4] + g_cnt[3] + g_cnt[2];
}
__global__ void sort3_k(const int* __restrict__ lengths, int B) {
    int i = blockIdx.x * 256 + threadIdx.x;
    if (i < B) {
        int mt = (lengths[i] + 15) >> 4;
        int idx = atomicAdd(&g_cur[mt], 1);
        g_perm[idx] = i;
    }
}

// ============================================================================
// GEMM pieces (rmask masks the pos-bias row to the segment-local index)
// ============================================================================

template<int NT, bool PACKOUT>
__device__ __forceinline__ void gemm_big_t(
    const u32* Ah, const u32* Al, const uint4* __restrict__ Wp,
    const float* __restrict__ biasRows, const float* __restrict__ biasVec,
    u32* Ohh, u32* Ohl, float* Ofp, int mrow, int ntbase, bool active, int rmask)
{
    if (!active) return;
    const int lane = threadIdx.x & 31;
    const int g = lane >> 2, t = lane & 3;
    const int m0 = mrow << 4;
    const int lr = lane & 15, hb = lane >> 4;

    const u32 aH = s2u(Ah + (m0 + lr) * LDW + (hb << 2));
    const u32 aL = s2u(Al + (m0 + lr) * LDW + (hb << 2));

    float c[NT][4];
#pragma unroll
    for (int i = 0; i < NT; i++)
#pragma unroll
        for (int j = 0; j < 4; j++) c[i][j] = 0.0f;

#pragma unroll 2
    for (int s = 0; s < 16; s++) {
        u32 ah[4], al[4];
        ldsm4(aH + (s << 5), ah);
        ldsm4(aL + (s << 5), al);
        uint4 w[NT];
#pragma unroll
        for (int i = 0; i < NT; i++)
            w[i] = Wp[((ntbase + i) << 9) + (s << 5) + lane];
#pragma unroll
        for (int i = 0; i < NT; i++)
            mmab3(c[i], ah, al, w[i].x, w[i].y, w[i].z, w[i].w);
    }

#pragma unroll
    for (int nt = 0; nt < NT; nt++) {
        int col = ((ntbase + nt) << 3) + (t << 1);
        if (PACKOUT) {
            int rA = (m0 + g) & rmask, rB = (m0 + 8 + g) & rmask;
            float2 bA = *(const float2*)(biasRows + rA * 256 + col);
            float2 bB = *(const float2*)(biasRows + rB * 256 + col);
            u32 hw, lw;
            bsplit(c[nt][0] + bA.x, c[nt][1] + bA.y, hw, lw);
            Ohh[(m0 + g) * LDW + (col >> 1)] = hw;
            Ohl[(m0 + g) * LDW + (col >> 1)] = lw;
            bsplit(c[nt][2] + bB.x, c[nt][3] + bB.y, hw, lw);
            Ohh[(m0 + 8 + g) * LDW + (col >> 1)] = hw;
            Ohl[(m0 + 8 + g) * LDW + (col >> 1)] = lw;
        } else {
            float2 bb = *(const float2*)(biasVec + col);
            *(float2*)(Ofp + (m0 + g) * LDO + col) =
                make_float2(c[nt][0] + bb.x, c[nt][1] + bb.y);
            *(float2*)(Ofp + (m0 + 8 + g) * LDO + col) =
                make_float2(c[nt][2] + bb.x, c[nt][3] + bb.y);
        }
    }
}

template<int NT>
__device__ __forceinline__ void gemm_kv_t(
    const u32* Ah, const u32* Al, int h,
    u32* Khh, u32* Khl, u16* Vhh16, u16* Vhl16,
    int mrow, int ntl, bool active, int isV, int rmask)
{
    if (!active) return;
    const int lane = threadIdx.x & 31;
    const int g = lane >> 2, t = lane & 3;
    const int m0 = mrow << 4;
    const uint4* __restrict__ Wp = g_wr + ((1 + isV) << 14);
    const float* __restrict__ biasRows = g_posb + ((1 + isV) << 14);
    const int lr = lane & 15, hb = lane >> 4;

    const u32 aH = s2u(Ah + (m0 + lr) * LDW + (hb << 2));
    const u32 aL = s2u(Al + (m0 + lr) * LDW + (hb << 2));

    float c[NT][4];
#pragma unroll
    for (int i = 0; i < NT; i++)
#pragma unroll
        for (int j = 0; j < 4; j++) c[i][j] = 0.0f;

#pragma unroll 2
    for (int s = 0; s < 16; s++) {
        u32 ah[4], al[4];
        ldsm4(aH + (s << 5), ah);
        ldsm4(aL + (s << 5), al);
        uint4 w[NT];
#pragma unroll
        for (int i = 0; i < NT; i++)
            w[i] = Wp[(((h << 3) + ntl + i) << 9) + (s << 5) + lane];
#pragma unroll
        for (int i = 0; i < NT; i++)
            mmab3(c[i], ah, al, w[i].x, w[i].y, w[i].z, w[i].w);
    }

#pragma unroll
    for (int nt = 0; nt < NT; nt++) {
        int nl = ((ntl + nt) << 3) + (t << 1);
        int colg = (h << 6) + nl;
        int rA = (m0 + g) & rmask, rB = (m0 + 8 + g) & rmask;
        float2 bA = *(const float2*)(biasRows + rA * 256 + colg);
        float2 bB = *(const float2*)(biasRows + rB * 256 + colg);
        if (!isV) {
            u32 hw, lww;
            bsplit(c[nt][0] + bA.x, c[nt][1] + bA.y, hw, lww);
            Khh[(m0 + g) * LDWK + (nl >> 1)] = hw;
            Khl[(m0 + g) * LDWK + (nl >> 1)] = lww;
            bsplit(c[nt][2] + bB.x, c[nt][3] + bB.y, hw, lww);
            Khh[(m0 + 8 + g) * LDWK + (nl >> 1)] = hw;
            Khl[(m0 + 8 + g) * LDWK + (nl >> 1)] = lww;
        } else {
            int m = m0 + g;
            u32 hw, lww;
            bsplit(c[nt][0] + bA.x, c[nt][1] + bA.y, hw, lww);
            Vhh16[nl * 72 + m]       = (u16)hw;
            Vhh16[(nl + 1) * 72 + m] = (u16)(hw >> 16);
            Vhl16[nl * 72 + m]       = (u16)lww;
            Vhl16[(nl + 1) * 72 + m] = (u16)(lww >> 16);
            bsplit(c[nt][2] + bB.x, c[nt][3] + bB.y, hw, lww);
            Vhh16[nl * 72 + m + 8]       = (u16)hw;
            Vhh16[(nl + 1) * 72 + m + 8] = (u16)(hw >> 16);
            Vhl16[nl * 72 + m + 8]       = (u16)lww;
            Vhl16[(nl + 1) * 72 + m + 8] = (u16)(lww >> 16);
        }
    }
}

// scores: block-diagonal active set per mode
__device__ __forceinline__ void gemm_scores(
    const u32* Qhh, const u32* Qhl, int h,
    const u32* Khh, const u32* Khl, float* Ss, int mode, int mtiles)
{
    const int wid = threadIdx.x >> 5, lane = threadIdx.x & 31;
    const int mrow = wid & 3, nc8 = wid >> 2;
    bool act;
    if (mode == 0)      act = (mrow < mtiles) && (nc8 < (mtiles << 1));
    else if (mode == 1) act = (nc8 >> 2) == (mrow >> 1);
    else                act = (nc8 >> 1) == mrow;
    if (!act) return;
    const int g = lane >> 2, t = lane & 3;
    const int m0 = mrow << 4;
    const int lr = lane & 15, hb = lane >> 4;

    const u32 aH = s2u(Qhh + (m0 + lr) * LDW + (h << 5) + (hb << 2));
    const u32 aL = s2u(Qhl + (m0 + lr) * LDW + (h << 5) + (hb << 2));
    const int brow = (nc8 << 3) + (lane & 7);
    const int boff = ((lane >> 3) & 1) << 2;
    const u32 bH = s2u(Khh + brow * LDWK + boff);
    const u32 bL = s2u(Khl + brow * LDWK + boff);

    float c[4];
#pragma unroll
    for (int j = 0; j < 4; j++) c[j] = 0.0f;

#pragma unroll
    for (int s = 0; s < 4; s++) {
        u32 ah[4], al[4], kh[2], kl[2];
        ldsm4(aH + (s << 5), ah);
        ldsm4(aL + (s << 5), al);
        ldsm2(bH + (s << 5), kh);
        ldsm2(bL + (s << 5), kl);
        mmab3(c, ah, al, kh[0], kh[1], kl[0], kl[1]);
    }

    int n0 = (nc8 << 3) + (t << 1);
    *(float2*)(Ss + (m0 + g) * LDF + n0)     = make_float2(c[0], c[1]);
    *(float2*)(Ss + (m0 + 8 + g) * LDF + n0) = make_float2(c[2], c[3]);
}

__device__ __forceinline__ void gemm_pv(
    const u32* Phh, const u32* Phl, const u32* Vhh, const u32* Vhl, int h,
    u32* Qhh, u32* Qhl, int mtiles)
{
    const int wid = threadIdx.x >> 5, lane = threadIdx.x & 31;
    const int mrow = wid & 3, nc8 = wid >> 2;
    if (mrow >= mtiles) return;
    const int g = lane >> 2, t = lane & 3;
    const int m0 = mrow << 4;
    const int lr = lane & 15, hb = lane >> 4;

    const u32 aH = s2u(Phh + (m0 + lr) * LDWK + (hb << 2));
    const u32 aL = s2u(Phl + (m0 + lr) * LDWK + (hb << 2));
    const int brow = (nc8 << 3) + (lane & 7);
    const int boff = ((lane >> 3) & 1) << 2;
    const u32 bH = s2u(Vhh + brow * LDWK + boff);
    const u32 bL = s2u(Vhl + brow * LDWK + boff);

    float c[4];
#pragma unroll
    for (int j = 0; j < 4; j++) c[j] = 0.0f;

    for (int s = 0; s < mtiles; s++) {
        u32 ah[4], al[4], vh[2], vl[2];
        ldsm4(aH + (s << 5), ah);
        ldsm4(aL + (s << 5), al);
        ldsm2(bH + (s << 5), vh);
        ldsm2(bL + (s << 5), vl);
        mmab3(c, ah, al, vh[0], vh[1], vl[0], vl[1]);
    }

    int coll = (nc8 << 3) + (t << 1);
    int wrd = (h << 5) + (coll >> 1);
    u32 hw, lw;
    bsplit(c[0], c[1], hw, lw);
    Qhh[(m0 + g) * LDW + wrd] = hw;
    Qhl[(m0 + g) * LDW + wrd] = lw;
    bsplit(c[2], c[3], hw, lw);
    Qhh[(m0 + 8 + g) * LDW + wrd] = hw;
    Qhl[(m0 + 8 + g) * LDW + wrd] = lw;
}

// ============================================================================
__global__ void __launch_bounds__(1024, 1)
enc_kernel(const float* __restrict__ obstacles, const int* __restrict__ lengths,
           const float* __restrict__ w1, const float* __restrict__ b1,
           const float* __restrict__ bo)
{
    // ---- CTA composition from counting-sort offsets ----
    const int c4 = g_cnt[4], c3 = g_cnt[3], c2 = g_cnt[2], c1 = g_cnt[1];
    const int n4 = c4, n3 = c3, n2 = (c2 + 1) >> 1, n1 = (c1 + 3) >> 2;
    const int i = blockIdx.x;
    if (i >= n4 + n3 + n2 + n1) return;

    int mode, mtiles, segshift;
    int segb[4] = {-1, -1, -1, -1};
    if (i < n4) {
        mode = 0; mtiles = 4; segshift = 6;
        segb[0] = g_perm[i];
    } else if (i < n4 + n3) {
        mode = 0; mtiles = 3; segshift = 6;
        segb[0] = g_perm[c4 + (i - n4)];
    } else if (i < n4 + n3 + n2) {
        int j = i - n4 - n3;
        mode = 1; mtiles = 4; segshift = 5;
        int base = c4 + c3 + (j << 1);
        segb[0] = g_perm[base];
        if ((j << 1) + 1 < c2) segb[1] = g_perm[base + 1];
    } else {
        int j = i - n4 - n3 - n2;
        mode = 2; mtiles = 4; segshift = 4;
        int base = c4 + c3 + c2 + (j << 2);
#pragma unroll
        for (int s = 0; s < 4; s++)
            if ((j << 2) + s < c1) segb[s] = g_perm[base + s];
    }
    const int rps = 1 << segshift;
    const int rmask = rps - 1;
    const int nseg = (mode == 0) ? 1 : (mode == 1) ? 2 : 4;
    int seglen[4];
#pragma unroll
    for (int s = 0; s < 4; s++)
        seglen[s] = (segb[s] >= 0) ? lengths[segb[s]] : 0;

    extern __shared__ float sm[];
    u32* Thh = (u32*)(sm + OFF_THH);
    u32* Thl = (u32*)(sm + OFF_THL);
    u32* Qhh = (u32*)(sm + OFF_QHH);
    u32* Qhl = (u32*)(sm + OFF_QHL);
    u32* Khh = (u32*)(sm + OFF_KHH);
    u32* Khl = (u32*)(sm + OFF_KHL);
    u32* Phh = (u32*)(sm + OFF_PHH);
    u32* Phl = (u32*)(sm + OFF_PHL);
    u32* Vhh = (u32*)(sm + OFF_VHH);
    u32* Vhl = (u32*)(sm + OFF_VHL);
    u16* Vhh16 = (u16*)Vhh;
    u16* Vhl16 = (u16*)Vhl;
    float* Ss  = sm + OFF_S;
    float* ws  = sm + OFF_WS;
    float* OutT = sm + OFF_OUT;

    const int tid = threadIdx.x;
    const int wid = tid >> 5, lane = tid & 31;

    // ---- stage w1 + per-segment obstacles (zero-padded) ----
    if (tid < 256) {
        *(float4*)(ws + WS_W1 + (tid << 2)) = *(const float4*)(w1 + (tid << 2));
        int row = tid >> 2, f = tid & 3;
        int s = row >> segshift, local = row & rmask;
        float v = 0.0f;
        if (segb[s] >= 0 && local < seglen[s])
            v = obstacles[segb[s] * 256 + (local << 2) + f];
        ws[WS_OBS + tid] = v;
    }
    __syncthreads();

    // ---- phase 1: t = relu(obs @ w1 + b1), rows < 16*mtiles ----
    {
        int cp = tid & 127, q = tid >> 7;
        int c0 = cp << 1;
        float wa0 = ws[WS_W1 + c0],       wa1 = ws[WS_W1 + c0 + 1];
        float wb0 = ws[WS_W1 + 256 + c0], wb1 = ws[WS_W1 + 256 + c0 + 1];
        float wc0 = ws[WS_W1 + 512 + c0], wc1 = ws[WS_W1 + 512 + c0 + 1];
        float wd0 = ws[WS_W1 + 768 + c0], wd1 = ws[WS_W1 + 768 + c0 + 1];
        float bb0 = b1[c0], bb1 = b1[c0 + 1];
        if (q < (mtiles << 1)) {
            int n0 = q << 3;
#pragma unroll 4
            for (int n = n0; n < n0 + 8; n++) {
                float4 o = *(const float4*)(ws + WS_OBS + (n << 2));
                float v0 = fmaf(o.x, wa0, fmaf(o.y, wb0, fmaf(o.z, wc0, fmaf(o.w, wd0, bb0))));
                float v1 = fmaf(o.x, wa1, fmaf(o.y, wb1, fmaf(o.z, wc1, fmaf(o.w, wd1, bb1))));
                v0 = fmaxf(v0, 0.0f); v1 = fmaxf(v1, 0.0f);
                u32 hw, lw;
                bsplit(v0, v1, hw, lw);
                Thh[n * LDW + cp] = hw;
                Thl[n * LDW + cp] = lw;
            }
        }
    }
    __syncthreads();

    // ---- Q = t @ wq' + posb (rmask'd), packed ----
    gemm_big_t<4, true>(Thh, Thl, g_wr, g_posb, nullptr, Qhh, Qhl, nullptr,
                        wid & 3, (wid >> 2) << 2, (wid & 3) < mtiles, rmask);
    __syncthreads();

    // ---- attention heads ----
    const int isV = wid >> 4, lw_ = wid & 15;
#pragma unroll 1
    for (int h = 0; h < 4; h++) {
        gemm_kv_t<2>(Thh, Thl, h, Khh, Khl, Vhh16, Vhl16,
                     lw_ & 3, (lw_ >> 2) << 1, (lw_ & 3) < mtiles, isV, rmask);
        __syncthreads();

        gemm_scores(Qhh, Qhl, h, Khh, Khl, Ss, mode, mtiles);
        __syncthreads();

        // block-diagonal masked softmax; writes zeros outside segment range
        if (wid < (mtiles << 2)) {
            bool va[4], vb[4];
            // per-row values computed inside loop (rows have distinct segments
            // only across rr when rps==16? no: rows 4wid..4wid+3 same segment
            // unless rps==16 and wid*4 crosses... 4-row group always within one
            // 16-row segment block since (wid<<2)>>4 constant for rr<4.)
            int r0g = wid << 2;
            int s = r0g >> segshift;
            int c0 = s << segshift;
            int lenS = seglen[s];
            int col0 = lane << 1;
            bool v0 = (col0 >= c0) && (col0 < c0 + lenS);
            bool v1 = (col0 + 1 >= c0) && (col0 + 1 < c0 + lenS);
            (void)va; (void)vb;
#pragma unroll
            for (int rr = 0; rr < 4; rr++) {
                int r = r0g + rr;
                float2 x = *(const float2*)(Ss + r * LDF + col0);
                float m = fmaxf(v0 ? x.x : -3.4e38f, v1 ? x.y : -3.4e38f);
#pragma unroll
                for (int off = 16; off; off >>= 1)
                    m = fmaxf(m, __shfl_xor_sync(0xffffffffu, m, off));
                float e0 = v0 ? __expf(x.x - m) : 0.0f;
                float e1 = v1 ? __expf(x.y - m) : 0.0f;
                float sum = e0 + e1;
#pragma unroll
                for (int off = 16; off; off >>= 1)
                    sum += __shfl_xor_sync(0xffffffffu, sum, off);
                float inv = __frcp_rn(sum);
                u32 hw, lw;
                bsplit(e0 * inv, e1 * inv, hw, lw);
                Phh[r * LDWK + lane] = hw;
                Phl[r * LDWK + lane] = lw;
            }
        }
        __syncthreads();

        gemm_pv(Phh, Phl, Vhh, Vhl, h, Qhh, Qhl, mtiles);
        __syncthreads();
    }

    // ---- out = ctx @ wo + bo -> OutT fp32 ----
    gemm_big_t<4, false>(Qhh, Qhl, g_wr + 3 * 16384, nullptr, bo,
                         nullptr, nullptr, OutT, wid & 3, (wid >> 2) << 2,
                         (wid & 3) < mtiles, rmask);
    __syncthreads();

    // ---- per-segment masked mean/max pool -> g_pool ----
    {
        int col = tid & 255, ch = tid >> 8;     // chunk of 16 rows
        int s = (mode == 0) ? 0 : (mode == 1) ? (ch >> 1) : ch;
        int lo = (mode == 0) ? (ch << 4) : (mode == 1) ? ((ch & 1) << 4) : 0;
        int lenS = seglen[s];
        int cnt = lenS - lo;
        cnt = cnt < 0 ? 0 : (cnt > 16 ? 16 : cnt);
        int r0 = ch << 4;
        float sum = 0.0f, mx = -3.4e38f;
        for (int n = r0; n < r0 + cnt; n++) {
            float x = OutT[n * LDO + col];
            sum += x; mx = fmaxf(mx, x);
        }
        ws[WS_PS + tid] = sum;
        ws[WS_PM + tid] = mx;
    }
    __syncthreads();
    if (tid < 256) {
        int col = tid;
        int chPerSeg = rps >> 4;
        for (int s = 0; s < nseg; s++) {
            int bS = segb[s];
            if (bS < 0) continue;
            int lenS = seglen[s];
            if (lenS <= 0) continue;
            int ch0 = s * chPerSeg;
            float sum = 0.0f, mx = -3.4e38f;
            for (int c = ch0; c < ch0 + chPerSeg; c++) {
                sum += ws[WS_PS + (c << 8) + col];
                mx = fmaxf(mx, ws[WS_PM + (c << 8) + col]);
            }
            g_pool[bS * 512 + col]       = sum / (float)lenS;
            g_pool[bS * 512 + 256 + col] = mx;
        }
    }
}

// ============================================================================
// Batched MLP + LayerNorm (unchanged from R14)
// ============================================================================
__global__ void __launch_bounds__(256, 1)
mlp_kernel(const float* __restrict__ g1w, const float* __restrict__ g1b,
           const float* __restrict__ g2w, const float* __restrict__ g2b,
           const float* __restrict__ ln_g, const float* __restrict__ ln_b,
           float* __restrict__ out, int B)
{
    extern __shared__ float ms[];
    float* gs  = ms;
    float* a1s = ms + 16384;
    float* red = ms + 24576;
    const int tid = threadIdx.x;
    const int r0 = blockIdx.x << 5;

    for (int i = tid; i < 4096; i += 256) {
        float4 v = make_float4(0.f, 0.f, 0.f, 0.f);
        if (r0 + (i >> 7) < B)
            v = ((const float4*)g_pool)[r0 * 128 + i];
        ((float4*)gs)[i] = v;
    }
    __syncthreads();

    float acc[32];
#pragma unroll
    for (int r = 0; r < 32; r++) acc[r] = 0.0f;
#pragma unroll 1
    for (int k4 = 0; k4 < 512; k4 += 4) {
        float w0 = g1w[k4 * 256 + tid];
        float w1 = g1w[(k4 + 1) * 256 + tid];
        float w2 = g1w[(k4 + 2) * 256 + tid];
        float w3 = g1w[(k4 + 3) * 256 + tid];
#pragma unroll
        for (int r = 0; r < 32; r++) {
            float4 g4 = *(const float4*)(gs + (r << 9) + k4);
            acc[r] = fmaf(g4.w, w3, fmaf(g4.z, w2, fmaf(g4.y, w1, fmaf(g4.x, w0, acc[r]))));
        }
    }
    {
        float bb = g1b[tid];
#pragma unroll
        for (int r = 0; r < 32; r++)
            a1s[(r << 8) + tid] = fmaxf(acc[r] + bb, 0.0f);
    }
    __syncthreads();

#pragma unroll
    for (int r = 0; r < 32; r++) acc[r] = 0.0f;
#pragma unroll 1
    for (int k4 = 0; k4 < 256; k4 += 4) {
        float w0 = g2w[k4 * 256 + tid];
        float w1 = g2w[(k4 + 1) * 256 + tid];
        float w2 = g2w[(k4 + 2) * 256 + tid];
        float w3 = g2w[(k4 + 3) * 256 + tid];
#pragma unroll
        for (int r = 0; r < 32; r++) {
            float4 a4 = *(const float4*)(a1s + (r << 8) + k4);
            acc[r] = fmaf(a4.w, w3, fmaf(a4.z, w2, fmaf(a4.y, w1, fmaf(a4.x, w0, acc[r]))));
        }
    }
    __syncthreads();
    {
        float bb = g2b[tid];
#pragma unroll
        for (int r = 0; r < 32; r++)
            gs[(r << 8) + tid] = acc[r] + bb;
    }
    __syncthreads();

    const int r = tid >> 3, sub = tid & 7;
    const int c0 = sub << 5;
    float s = 0.0f;
#pragma unroll 8
    for (int c = c0; c < c0 + 32; c++) s += gs[(r << 8) + c];
    red[(r << 3) + sub] = s;
    __syncthreads();
    float mu = 0.0f;
#pragma unroll
    for (int i = 0; i < 8; i++) mu += red[(r << 3) + i];
    mu *= (1.0f / 256.0f);
    __syncthreads();
    float s2 = 0.0f;
#pragma unroll 8
    for (int c = c0; c < c0 + 32; c++) {
        float d = gs[(r << 8) + c] - mu;
        s2 += d * d;
    }
    red[(r << 3) + sub] = s2;
    __syncthreads();
    float var = 0.0f;
#pragma unroll
    for (int i = 0; i < 8; i++) var += red[(r << 3) + i];
    var *= (1.0f / 256.0f);
    float rstd = rsqrtf(var + 1e-5f);
    if (r0 + r < B) {
#pragma unroll 8
        for (int c = c0; c < c0 + 32; c++)
            out[(r0 + r) * 256 + c] =
                (gs[(r << 8) + c] - mu) * rstd * ln_g[c] + ln_b[c];
    }
}

// ---------------------------------------------------------------------------
extern "C" void kernel_launch(void* const* d_in, const int* in_sizes, int n_in,
                              void* d_out, int out_size)
{
    const float* obstacles = (const float*)d_in[0];
    const int*   lengths   = (const int*)d_in[1];
    const float* w1   = (const float*)d_in[2];
    const float* b1   = (const float*)d_in[3];
    const float* w2   = (const float*)d_in[4];
    const float* b2   = (const float*)d_in[5];
    const float* pos  = (const float*)d_in[6];
    const float* wq   = (const float*)d_in[7];
    const float* bq   = (const float*)d_in[8];
    const float* wk   = (const float*)d_in[9];
    const float* bk   = (const float*)d_in[10];
    const float* wv   = (const float*)d_in[11];
    const float* bv   = (const float*)d_in[12];
    const float* wo   = (const float*)d_in[13];
    const float* bo   = (const float*)d_in[14];
    const float* g1w  = (const float*)d_in[15];
    const float* g1b  = (const float*)d_in[16];
    const float* g2w  = (const float*)d_in[17];
    const float* g2b  = (const float*)d_in[18];
    const float* ln_g = (const float*)d_in[19];
    const float* ln_b = (const float*)d_in[20];
    float* out = (float*)d_out;

    const int B = in_sizes[1];
    const int gB = (B + 255) / 256;

    sort0_k<<<1, 32>>>();
    sort1_k<<<gB, 256>>>(lengths, B);
    sort2_k<<<1, 1>>>();
    sort3_k<<<gB, 256>>>(lengths, B);

    fold_k<<<768, 256>>>(w2, wq, wk, wv);
    posfold_k<<<192, 256>>>(pos, b2, wq, wk, wv, bq, bk, bv);
    pack_k<<<256, 256>>>(wo);

    cudaFuncSetAttribute(enc_kernel, cudaFuncAttributeMaxDynamicSharedMemorySize, SMEM_BYTES);
    enc_kernel<<<B, 1024, SMEM_BYTES>>>(obstacles, lengths, w1, b1, bo);

    cudaFuncSetAttribute(mlp_kernel, cudaFuncAttributeMaxDynamicSharedMemorySize, MLP_SMEM);
    mlp_kernel<<<(B + 31) / 32, 256, MLP_SMEM>>>(g1w, g1b, g2w, g2b, ln_g, ln_b, out, B);
}

// round 17
// speedup vs baseline: 1.4480x; 1.0146x over previous
#include <cuda_runtime.h>

// ============================================================================
// AttentionObstacleEncoder via bf16 mma.sync.m16n8k16, 3-term hi/lo split.
// R17 = R16 (generalized packing w/ per-tile segment tables), re-audited and
// resubmitted after infra failure.
// CTA compositions (64-row frame, 16-row tiles):
//   mt4 single     : tiles {0,0,0,0}
//   mt3 + mt1 pair : tiles {0,0,0,1}, segstart {0,48}
//   mt3 single     : tiles {0,0,0,-1}
//   mt2 + mt2 pair : tiles {0,0,1,1}, segstart {0,32}
//   mt1 quad       : tiles {0,1,2,3}, segstart {0,16,32,48}
// Block-diagonal attention via tileseg equality; softmax masks keys to each
// segment's [start, start+len); pos-bias row = row - segstart. Invalid tiles
// never read. CTA count ~2816 -> ~2560 at equal FLOPs.
// Plus batched MLP kernel and LPT ordering.
// ============================================================================

typedef unsigned int u32;
typedef unsigned short u16;

#define LDW  132
#define LDWK 36
#define LDF  68
#define LDO  260

#define OFF_THH  0
#define OFF_THL  8448
#define OFF_QHH  16896
#define OFF_QHL  25344
#define OFF_KHH  33792
#define OFF_KHL  36096
#define OFF_PHH  38400
#define OFF_PHL  40704
#define OFF_VHH  43008
#define OFF_VHL  45312
#define OFF_S    47616
#define OFF_OUT  0
#define OFF_WS   33792
#define SMEM_WORDS 51968
#define SMEM_BYTES (SMEM_WORDS * 4)

#define WS_PS   0
#define WS_PM   1024
#define WS_OBS  2048
#define WS_W1   2304

#define MLP_SMEM (24832 * 4)

__device__ float g_wf[3 * 65536];
__device__ float g_posb[3 * 16384];
__device__ uint4 g_wr[4 * 16384];
__device__ float g_pool[4096 * 512];
__device__ int   g_cnt[5];
__device__ int   g_cur[5];
__device__ int   g_perm[8192];

__device__ __forceinline__ u32 packbf(float x0, float x1) {
    u32 r; asm("cvt.rn.bf16x2.f32 %0, %2, %1;" : "=r"(r) : "f"(x0), "f"(x1));
    return r;
}
__device__ __forceinline__ void bsplit(float x0, float x1, u32& hw, u32& lw) {
    hw = packbf(x0, x1);
    float h0 = __uint_as_float(hw << 16);
    float h1 = __uint_as_float(hw & 0xffff0000u);
    lw = packbf(x0 - h0, x1 - h1);
}
__device__ __forceinline__ void mmab(float* c, u32 a0, u32 a1, u32 a2, u32 a3,
                                     u32 b0, u32 b1) {
    asm("mma.sync.aligned.m16n8k16.row.col.f32.bf16.bf16.f32 "
        "{%0,%1,%2,%3},{%4,%5,%6,%7},{%8,%9},{%0,%1,%2,%3};"
        : "+f"(c[0]), "+f"(c[1]), "+f"(c[2]), "+f"(c[3])
        : "r"(a0), "r"(a1), "r"(a2), "r"(a3), "r"(b0), "r"(b1));
}
__device__ __forceinline__ void mmab3(float* c, const u32* ah, const u32* al,
                                      u32 bh0, u32 bh1, u32 bl0, u32 bl1) {
    mmab(c, ah[0], ah[1], ah[2], ah[3], bl0, bl1);
    mmab(c, al[0], al[1], al[2], al[3], bh0, bh1);
    mmab(c, ah[0], ah[1], ah[2], ah[3], bh0, bh1);
}
__device__ __forceinline__ u32 s2u(const void* p) {
    return (u32)__cvta_generic_to_shared(p);
}
__device__ __forceinline__ void ldsm4(u32 addr, u32* r) {
    asm volatile("ldmatrix.sync.aligned.m8n8.x4.shared.b16 {%0,%1,%2,%3}, [%4];"
        : "=r"(r[0]), "=r"(r[1]), "=r"(r[2]), "=r"(r[3]) : "r"(addr));
}
__device__ __forceinline__ void ldsm2(u32 addr, u32* r) {
    asm volatile("ldmatrix.sync.aligned.m8n8.x2.shared.b16 {%0,%1}, [%2];"
        : "=r"(r[0]), "=r"(r[1]) : "r"(addr));
}

// ============================================================================
// Prep kernels
// ============================================================================

__global__ void fold_k(const float* __restrict__ w2, const float* __restrict__ wq,
                       const float* __restrict__ wk, const float* __restrict__ wv)
{
    int m = blockIdx.x >> 8, k = blockIdx.x & 255, c = threadIdx.x;
    const float* wx = (m == 0) ? wq : (m == 1) ? wk : wv;
    float acc = 0.0f;
#pragma unroll 8
    for (int d = 0; d < 256; d++)
        acc = fmaf(__ldg(w2 + k * 256 + d), __ldg(wx + d * 256 + c), acc);
    if (m == 0) acc *= 0.125f;
    g_wf[m * 65536 + k * 256 + c] = acc;
}

__global__ void posfold_k(const float* __restrict__ pos, const float* __restrict__ b2,
                          const float* __restrict__ wq, const float* __restrict__ wk,
                          const float* __restrict__ wv, const float* __restrict__ bq,
                          const float* __restrict__ bk, const float* __restrict__ bv)
{
    int m = blockIdx.x >> 6, n = blockIdx.x & 63, c = threadIdx.x;
    const float* wx = (m == 0) ? wq : (m == 1) ? wk : wv;
    const float* bx = (m == 0) ? bq : (m == 1) ? bk : bv;
    float acc = __ldg(bx + c);
#pragma unroll 8
    for (int d = 0; d < 256; d++)
        acc = fmaf(__ldg(pos + n * 256 + d) + __ldg(b2 + d), __ldg(wx + d * 256 + c), acc);
    if (m == 0) acc *= 0.125f;
    g_posb[m * 16384 + n * 256 + c] = acc;
}

__global__ void pack_k(const float* __restrict__ wo)
{
    int idx = blockIdx.x * 256 + threadIdx.x;
    int m = idx >> 14;
    int u = idx & 16383;
    int ntile = u >> 9;
    int s = (u >> 5) & 15;
    int lane = u & 31;
    int g = lane >> 2, t = lane & 3;
    int n = ntile * 8 + g;
    int k0 = s * 16 + t * 2;
    const float* W = (m < 3) ? (g_wf + m * 65536) : wo;
    float f0 = W[k0 * 256 + n];
    float f1 = W[(k0 + 1) * 256 + n];
    float f2 = W[(k0 + 8) * 256 + n];
    float f3 = W[(k0 + 9) * 256 + n];
    uint4 r;
    bsplit(f0, f1, r.x, r.z);
    bsplit(f2, f3, r.y, r.w);
    g_wr[idx] = r;
}

__global__ void sort0_k() {
    if (threadIdx.x < 5) { g_cnt[threadIdx.x] = 0; g_cur[threadIdx.x] = 0; }
}
__global__ void sort1_k(const int* __restrict__ lengths, int B) {
    int i = blockIdx.x * 256 + threadIdx.x;
    if (i < B) atomicAdd(&g_cnt[(lengths[i] + 15) >> 4], 1);
}
__global__ void sort2_k() {
    g_cur[4] = 0;
    g_cur[3] = g_cnt[4];
    g_cur[2] = g_cnt[4] + g_cnt[3];
    g_cur[1] = g_cnt[4] + g_cnt[3] + g_cnt[2];
}
__global__ void sort3_k(const int* __restrict__ lengths, int B) {
    int i = blockIdx.x * 256 + threadIdx.x;
    if (i < B) {
        int mt = (lengths[i] + 15) >> 4;
        int idx = atomicAdd(&g_cur[mt], 1);
        g_perm[idx] = i;
    }
}

// ============================================================================
// GEMM pieces (bsub = segment start row, subtracted for pos-bias lookup)
// ============================================================================

template<int NT, bool PACKOUT>
__device__ __forceinline__ void gemm_big_t(
    const u32* Ah, const u32* Al, const uint4* __restrict__ Wp,
    const float* __restrict__ biasRows, const float* __restrict__ biasVec,
    u32* Ohh, u32* Ohl, float* Ofp, int mrow, int ntbase, bool active, int bsub)
{
    if (!active) return;
    const int lane = threadIdx.x & 31;
    const int g = lane >> 2, t = lane & 3;
    const int m0 = mrow << 4;
    const int lr = lane & 15, hb = lane >> 4;

    const u32 aH = s2u(Ah + (m0 + lr) * LDW + (hb << 2));
    const u32 aL = s2u(Al + (m0 + lr) * LDW + (hb << 2));

    float c[NT][4];
#pragma unroll
    for (int i = 0; i < NT; i++)
#pragma unroll
        for (int j = 0; j < 4; j++) c[i][j] = 0.0f;

#pragma unroll 2
    for (int s = 0; s < 16; s++) {
        u32 ah[4], al[4];
        ldsm4(aH + (s << 5), ah);
        ldsm4(aL + (s << 5), al);
        uint4 w[NT];
#pragma unroll
        for (int i = 0; i < NT; i++)
            w[i] = Wp[((ntbase + i) << 9) + (s << 5) + lane];
#pragma unroll
        for (int i = 0; i < NT; i++)
            mmab3(c[i], ah, al, w[i].x, w[i].y, w[i].z, w[i].w);
    }

#pragma unroll
    for (int nt = 0; nt < NT; nt++) {
        int col = ((ntbase + nt) << 3) + (t << 1);
        if (PACKOUT) {
            int rA = m0 + g - bsub, rB = m0 + 8 + g - bsub;
            float2 bA = *(const float2*)(biasRows + rA * 256 + col);
            float2 bB = *(const float2*)(biasRows + rB * 256 + col);
            u32 hw, lw;
            bsplit(c[nt][0] + bA.x, c[nt][1] + bA.y, hw, lw);
            Ohh[(m0 + g) * LDW + (col >> 1)] = hw;
            Ohl[(m0 + g) * LDW + (col >> 1)] = lw;
            bsplit(c[nt][2] + bB.x, c[nt][3] + bB.y, hw, lw);
            Ohh[(m0 + 8 + g) * LDW + (col >> 1)] = hw;
            Ohl[(m0 + 8 + g) * LDW + (col >> 1)] = lw;
        } else {
            float2 bb = *(const float2*)(biasVec + col);
            *(float2*)(Ofp + (m0 + g) * LDO + col) =
                make_float2(c[nt][0] + bb.x, c[nt][1] + bb.y);
            *(float2*)(Ofp + (m0 + 8 + g) * LDO + col) =
                make_float2(c[nt][2] + bb.x, c[nt][3] + bb.y);
        }
    }
}

template<int NT>
__device__ __forceinline__ void gemm_kv_t(
    const u32* Ah, const u32* Al, int h,
    u32* Khh, u32* Khl, u16* Vhh16, u16* Vhl16,
    int mrow, int ntl, bool active, int isV, int bsub)
{
    if (!active) return;
    const int lane = threadIdx.x & 31;
    const int g = lane >> 2, t = lane & 3;
    const int m0 = mrow << 4;
    const uint4* __restrict__ Wp = g_wr + ((1 + isV) << 14);
    const float* __restrict__ biasRows = g_posb + ((1 + isV) << 14);
    const int lr = lane & 15, hb = lane >> 4;

    const u32 aH = s2u(Ah + (m0 + lr) * LDW + (hb << 2));
    const u32 aL = s2u(Al + (m0 + lr) * LDW + (hb << 2));

    float c[NT][4];
#pragma unroll
    for (int i = 0; i < NT; i++)
#pragma unroll
        for (int j = 0; j < 4; j++) c[i][j] = 0.0f;

#pragma unroll 2
    for (int s = 0; s < 16; s++) {
        u32 ah[4], al[4];
        ldsm4(aH + (s << 5), ah);
        ldsm4(aL + (s << 5), al);
        uint4 w[NT];
#pragma unroll
        for (int i = 0; i < NT; i++)
            w[i] = Wp[(((h << 3) + ntl + i) << 9) + (s << 5) + lane];
#pragma unroll
        for (int i = 0; i < NT; i++)
            mmab3(c[i], ah, al, w[i].x, w[i].y, w[i].z, w[i].w);
    }

#pragma unroll
    for (int nt = 0; nt < NT; nt++) {
        int nl = ((ntl + nt) << 3) + (t << 1);
        int colg = (h << 6) + nl;
        int rA = m0 + g - bsub, rB = m0 + 8 + g - bsub;
        float2 bA = *(const float2*)(biasRows + rA * 256 + colg);
        float2 bB = *(const float2*)(biasRows + rB * 256 + colg);
        if (!isV) {
            u32 hw, lww;
            bsplit(c[nt][0] + bA.x, c[nt][1] + bA.y, hw, lww);
            Khh[(m0 + g) * LDWK + (nl >> 1)] = hw;
            Khl[(m0 + g) * LDWK + (nl >> 1)] = lww;
            bsplit(c[nt][2] + bB.x, c[nt][3] + bB.y, hw, lww);
            Khh[(m0 + 8 + g) * LDWK + (nl >> 1)] = hw;
            Khl[(m0 + 8 + g) * LDWK + (nl >> 1)] = lww;
        } else {
            int m = m0 + g;
            u32 hw, lww;
            bsplit(c[nt][0] + bA.x, c[nt][1] + bA.y, hw, lww);
            Vhh16[nl * 72 + m]       = (u16)hw;
            Vhh16[(nl + 1) * 72 + m] = (u16)(hw >> 16);
            Vhl16[nl * 72 + m]       = (u16)lww;
            Vhl16[(nl + 1) * 72 + m] = (u16)(lww >> 16);
            bsplit(c[nt][2] + bB.x, c[nt][3] + bB.y, hw, lww);
            Vhh16[nl * 72 + m + 8]       = (u16)hw;
            Vhh16[(nl + 1) * 72 + m + 8] = (u16)(hw >> 16);
            Vhl16[nl * 72 + m + 8]       = (u16)lww;
            Vhl16[(nl + 1) * 72 + m + 8] = (u16)(lww >> 16);
        }
    }
}

__device__ __forceinline__ void gemm_scores(
    const u32* Qhh, const u32* Qhl, int h,
    const u32* Khh, const u32* Khl, float* Ss, bool act)
{
    if (!act) return;
    const int wid = threadIdx.x >> 5, lane = threadIdx.x & 31;
    const int mrow = wid & 3, nc8 = wid >> 2;
    const int g = lane >> 2, t = lane & 3;
    const int m0 = mrow << 4;
    const int lr = lane & 15, hb = lane >> 4;

    const u32 aH = s2u(Qhh + (m0 + lr) * LDW + (h << 5) + (hb << 2));
    const u32 aL = s2u(Qhl + (m0 + lr) * LDW + (h << 5) + (hb << 2));
    const int brow = (nc8 << 3) + (lane & 7);
    const int boff = ((lane >> 3) & 1) << 2;
    const u32 bH = s2u(Khh + brow * LDWK + boff);
    const u32 bL = s2u(Khl + brow * LDWK + boff);

    float c[4];
#pragma unroll
    for (int j = 0; j < 4; j++) c[j] = 0.0f;

#pragma unroll
    for (int s = 0; s < 4; s++) {
        u32 ah[4], al[4], kh[2], kl[2];
        ldsm4(aH + (s << 5), ah);
        ldsm4(aL + (s << 5), al);
        ldsm2(bH + (s << 5), kh);
        ldsm2(bL + (s << 5), kl);
        mmab3(c, ah, al, kh[0], kh[1], kl[0], kl[1]);
    }

    int n0 = (nc8 << 3) + (t << 1);
    *(float2*)(Ss + (m0 + g) * LDF + n0)     = make_float2(c[0], c[1]);
    *(float2*)(Ss + (m0 + 8 + g) * LDF + n0) = make_float2(c[2], c[3]);
}

__device__ __forceinline__ void gemm_pv(
    const u32* Phh, const u32* Phl, const u32* Vhh, const u32* Vhl, int h,
    u32* Qhh, u32* Qhl, int mtiles)
{
    const int wid = threadIdx.x >> 5, lane = threadIdx.x & 31;
    const int mrow = wid & 3, nc8 = wid >> 2;
    if (mrow >= mtiles) return;
    const int g = lane >> 2, t = lane & 3;
    const int m0 = mrow << 4;
    const int lr = lane & 15, hb = lane >> 4;

    const u32 aH = s2u(Phh + (m0 + lr) * LDWK + (hb << 2));
    const u32 aL = s2u(Phl + (m0 + lr) * LDWK + (hb << 2));
    const int brow = (nc8 << 3) + (lane & 7);
    const int boff = ((lane >> 3) & 1) << 2;
    const u32 bH = s2u(Vhh + brow * LDWK + boff);
    const u32 bL = s2u(Vhl + brow * LDWK + boff);

    float c[4];
#pragma unroll
    for (int j = 0; j < 4; j++) c[j] = 0.0f;

    for (int s = 0; s < mtiles; s++) {
        u32 ah[4], al[4], vh[2], vl[2];
        ldsm4(aH + (s << 5), ah);
        ldsm4(aL + (s << 5), al);
        ldsm2(bH + (s << 5), vh);
        ldsm2(bL + (s << 5), vl);
        mmab3(c, ah, al, vh[0], vh[1], vl[0], vl[1]);
    }

    int coll = (nc8 << 3) + (t << 1);
    int wrd = (h << 5) + (coll >> 1);
    u32 hw, lw;
    bsplit(c[0], c[1], hw, lw);
    Qhh[(m0 + g) * LDW + wrd] = hw;
    Qhl[(m0 + g) * LDW + wrd] = lw;
    bsplit(c[2], c[3], hw, lw);
    Qhh[(m0 + 8 + g) * LDW + wrd] = hw;
    Qhl[(m0 + 8 + g) * LDW + wrd] = lw;
}

// ============================================================================
__global__ void __launch_bounds__(1024, 1)
enc_kernel(const float* __restrict__ obstacles, const int* __restrict__ lengths,
           const float* __restrict__ w1, const float* __restrict__ b1,
           const float* __restrict__ bo)
{
    // ---- CTA composition from counting-sort offsets ----
    const int c4 = g_cnt[4], c3 = g_cnt[3], c2 = g_cnt[2], c1 = g_cnt[1];
    const int n31 = c3 < c1 ? c3 : c1;          // 3+1 pairs
    const int n3s = c3 - n31;                   // mt3 singles
    const int n2p = (c2 + 1) >> 1;              // mt2 pairs
    const int c1r = c1 - n31;                   // leftover mt1
    const int n1q = (c1r + 3) >> 2;             // mt1 quads
    const int i = blockIdx.x;
    if (i >= c4 + n31 + n3s + n2p + n1q) return;

    const int base1 = c4 + c3 + c2;             // mt1 range start in perm
    int segb[4] = {-1, -1, -1, -1};
    int tileseg[4];
    int segstart[4] = {0, 0, 0, 0};
    int mtiles;

    if (i < c4) {
        segb[0] = g_perm[i];
        tileseg[0] = 0; tileseg[1] = 0; tileseg[2] = 0; tileseg[3] = 0;
        mtiles = 4;
    } else if (i < c4 + n31) {
        int j = i - c4;
        segb[0] = g_perm[c4 + j];               // mt3 -> rows 0..47
        segb[1] = g_perm[base1 + j];            // mt1 -> rows 48..63
        tileseg[0] = 0; tileseg[1] = 0; tileseg[2] = 0; tileseg[3] = 1;
        segstart[1] = 48;
        mtiles = 4;
    } else if (i < c4 + n31 + n3s) {
        int j = i - c4 - n31;
        segb[0] = g_perm[c4 + n31 + j];
        tileseg[0] = 0; tileseg[1] = 0; tileseg[2] = 0; tileseg[3] = -1;
        mtiles = 3;
    } else if (i < c4 + n31 + n3s + n2p) {
        int j = i - c4 - n31 - n3s;
        int base = c4 + c3 + (j << 1);
        segb[0] = g_perm[base];
        tileseg[0] = 0; tileseg[1] = 0;
        if ((j << 1) + 1 < c2) {
            segb[1] = g_perm[base + 1];
            tileseg[2] = 1; tileseg[3] = 1;
            segstart[1] = 32;
            mtiles = 4;
        } else {
            tileseg[2] = -1; tileseg[3] = -1;
            mtiles = 2;
        }
    } else {
        int j = i - c4 - n31 - n3s - n2p;
        int base = base1 + n31 + (j << 2);
        mtiles = 0;
#pragma unroll
        for (int s = 0; s < 4; s++) {
            if ((j << 2) + s < c1r) {
                segb[s] = g_perm[base + s];
                tileseg[s] = s;
                segstart[s] = s << 4;
                mtiles = s + 1;
            } else tileseg[s] = -1;
        }
    }
    int seglen[4];
#pragma unroll
    for (int s = 0; s < 4; s++)
        seglen[s] = (segb[s] >= 0) ? lengths[segb[s]] : 0;

    extern __shared__ float sm[];
    u32* Thh = (u32*)(sm + OFF_THH);
    u32* Thl = (u32*)(sm + OFF_THL);
    u32* Qhh = (u32*)(sm + OFF_QHH);
    u32* Qhl = (u32*)(sm + OFF_QHL);
    u32* Khh = (u32*)(sm + OFF_KHH);
    u32* Khl = (u32*)(sm + OFF_KHL);
    u32* Phh = (u32*)(sm + OFF_PHH);
    u32* Phl = (u32*)(sm + OFF_PHL);
    u32* Vhh = (u32*)(sm + OFF_VHH);
    u32* Vhl = (u32*)(sm + OFF_VHL);
    u16* Vhh16 = (u16*)Vhh;
    u16* Vhl16 = (u16*)Vhl;
    float* Ss  = sm + OFF_S;
    float* ws  = sm + OFF_WS;
    float* OutT = sm + OFF_OUT;

    const int tid = threadIdx.x;
    const int wid = tid >> 5, lane = tid & 31;

    // per-warp GEMM activity
    const int tb = wid & 3;
    const bool actb = tileseg[tb] >= 0;
    const int bsubb = actb ? segstart[tileseg[tb]] : 0;
    const int lw_ = wid & 15, isV = wid >> 4;
    const int tk = lw_ & 3;
    const bool actk = tileseg[tk] >= 0;
    const int bsubk = actk ? segstart[tileseg[tk]] : 0;
    const int nc8 = wid >> 2;
    const bool actS = actb && (tileseg[tb] == tileseg[nc8 >> 1]);

    // ---- stage w1 + per-segment obstacles (zero-padded) ----
    if (tid < 256) {
        *(float4*)(ws + WS_W1 + (tid << 2)) = *(const float4*)(w1 + (tid << 2));
        int row = tid >> 2, f = tid & 3;
        int s = tileseg[row >> 4];
        float v = 0.0f;
        if (s >= 0) {
            int local = row - segstart[s];
            if (local >= 0 && local < seglen[s])
                v = obstacles[segb[s] * 256 + (local << 2) + f];
        }
        ws[WS_OBS + tid] = v;
    }
    __syncthreads();

    // ---- phase 1: t = relu(obs @ w1 + b1) on valid tiles ----
    {
        int cp = tid & 127, q = tid >> 7;      // q = row octet 0..7
        int c0 = cp << 1;
        float wa0 = ws[WS_W1 + c0],       wa1 = ws[WS_W1 + c0 + 1];
        float wb0 = ws[WS_W1 + 256 + c0], wb1 = ws[WS_W1 + 256 + c0 + 1];
        float wc0 = ws[WS_W1 + 512 + c0], wc1 = ws[WS_W1 + 512 + c0 + 1];
        float wd0 = ws[WS_W1 + 768 + c0], wd1 = ws[WS_W1 + 768 + c0 + 1];
        float bb0 = b1[c0], bb1 = b1[c0 + 1];
        if (tileseg[q >> 1] >= 0) {
            int n0 = q << 3;
#pragma unroll 4
            for (int n = n0; n < n0 + 8; n++) {
                float4 o = *(const float4*)(ws + WS_OBS + (n << 2));
                float v0 = fmaf(o.x, wa0, fmaf(o.y, wb0, fmaf(o.z, wc0, fmaf(o.w, wd0, bb0))));
                float v1 = fmaf(o.x, wa1, fmaf(o.y, wb1, fmaf(o.z, wc1, fmaf(o.w, wd1, bb1))));
                v0 = fmaxf(v0, 0.0f); v1 = fmaxf(v1, 0.0f);
                u32 hw, lw;
                bsplit(v0, v1, hw, lw);
                Thh[n * LDW + cp] = hw;
                Thl[n * LDW + cp] = lw;
            }
        }
    }
    __syncthreads();

    // ---- Q = t @ wq' + posb, packed ----
    gemm_big_t<4, true>(Thh, Thl, g_wr, g_posb, nullptr, Qhh, Qhl, nullptr,
                        tb, (wid >> 2) << 2, actb, bsubb);
    __syncthreads();

    // ---- attention heads ----
#pragma unroll 1
    for (int h = 0; h < 4; h++) {
        gemm_kv_t<2>(Thh, Thl, h, Khh, Khl, Vhh16, Vhl16,
                     tk, (lw_ >> 2) << 1, actk, isV, bsubk);
        __syncthreads();

        gemm_scores(Qhh, Qhl, h, Khh, Khl, Ss, actS);
        __syncthreads();

        // block-diagonal masked softmax (warp wid: rows 4wid..4wid+3)
        if (wid < 16 && tileseg[wid >> 2] >= 0) {
            int s = tileseg[wid >> 2];
            int c0 = segstart[s];
            int lenS = seglen[s];
            int col0 = lane << 1;
            bool v0 = (col0 >= c0) && (col0 < c0 + lenS);
            bool v1 = (col0 + 1 >= c0) && (col0 + 1 < c0 + lenS);
            int r0g = wid << 2;
#pragma unroll
            for (int rr = 0; rr < 4; rr++) {
                int r = r0g + rr;
                float2 x = *(const float2*)(Ss + r * LDF + col0);
                float m = fmaxf(v0 ? x.x : -3.4e38f, v1 ? x.y : -3.4e38f);
#pragma unroll
                for (int off = 16; off; off >>= 1)
                    m = fmaxf(m, __shfl_xor_sync(0xffffffffu, m, off));
                float e0 = v0 ? __expf(x.x - m) : 0.0f;
                float e1 = v1 ? __expf(x.y - m) : 0.0f;
                float sum = e0 + e1;
#pragma unroll
                for (int off = 16; off; off >>= 1)
                    sum += __shfl_xor_sync(0xffffffffu, sum, off);
                float inv = __frcp_rn(sum);
                u32 hw, lw;
                bsplit(e0 * inv, e1 * inv, hw, lw);
                Phh[r * LDWK + lane] = hw;
                Phl[r * LDWK + lane] = lw;
            }
        }
        __syncthreads();

        gemm_pv(Phh, Phl, Vhh, Vhl, h, Qhh, Qhl, mtiles);
        __syncthreads();
    }

    // ---- out = ctx @ wo + bo -> OutT fp32 ----
    gemm_big_t<4, false>(Qhh, Qhl, g_wr + 3 * 16384, nullptr, bo,
                         nullptr, nullptr, OutT, tb, (wid >> 2) << 2, actb, bsubb);
    __syncthreads();

    // ---- per-segment masked mean/max pool -> g_pool ----
    {
        int col = tid & 255, ch = tid >> 8;     // chunk = 16-row tile
        int s = tileseg[ch];
        float sum = 0.0f, mx = -3.4e38f;
        if (s >= 0) {
            int lo = (ch << 4) - segstart[s];
            int cnt = seglen[s] - lo;
            cnt = cnt < 0 ? 0 : (cnt > 16 ? 16 : cnt);
            int r0 = ch << 4;
            for (int n = r0; n < r0 + cnt; n++) {
                float x = OutT[n * LDO + col];
                sum += x; mx = fmaxf(mx, x);
            }
        }
        ws[WS_PS + tid] = sum;
        ws[WS_PM + tid] = mx;
    }
    __syncthreads();
    if (tid < 256) {
        int col = tid;
#pragma unroll
        for (int s = 0; s < 4; s++) {
            if (segb[s] < 0) continue;
            int lenS = seglen[s];
            if (lenS <= 0) continue;
            float sum = 0.0f, mx = -3.4e38f;
#pragma unroll
            for (int ch = 0; ch < 4; ch++) {
                if (tileseg[ch] == s) {
                    sum += ws[WS_PS + (ch << 8) + col];
                    mx = fmaxf(mx, ws[WS_PM + (ch << 8) + col]);
                }
            }
            g_pool[segb[s] * 512 + col]       = sum / (float)lenS;
            g_pool[segb[s] * 512 + 256 + col] = mx;
        }
    }
}

// ============================================================================
// Batched MLP + LayerNorm
// ============================================================================
__global__ void __launch_bounds__(256, 1)
mlp_kernel(const float* __restrict__ g1w, const float* __restrict__ g1b,
           const float* __restrict__ g2w, const float* __restrict__ g2b,
           const float* __restrict__ ln_g, const float* __restrict__ ln_b,
           float* __restrict__ out, int B)
{
    extern __shared__ float ms[];
    float* gs  = ms;
    float* a1s = ms + 16384;
    float* red = ms + 24576;
    const int tid = threadIdx.x;
    const int r0 = blockIdx.x << 5;

    for (int i = tid; i < 4096; i += 256) {
        float4 v = make_float4(0.f, 0.f, 0.f, 0.f);
        if (r0 + (i >> 7) < B)
            v = ((const float4*)g_pool)[r0 * 128 + i];
        ((float4*)gs)[i] = v;
    }
    __syncthreads();

    float acc[32];
#pragma unroll
    for (int r = 0; r < 32; r++) acc[r] = 0.0f;
#pragma unroll 1
    for (int k4 = 0; k4 < 512; k4 += 4) {
        float w0 = g1w[k4 * 256 + tid];
        float w1 = g1w[(k4 + 1) * 256 + tid];
        float w2 = g1w[(k4 + 2) * 256 + tid];
        float w3 = g1w[(k4 + 3) * 256 + tid];
#pragma unroll
        for (int r = 0; r < 32; r++) {
            float4 g4 = *(const float4*)(gs + (r << 9) + k4);
            acc[r] = fmaf(g4.w, w3, fmaf(g4.z, w2, fmaf(g4.y, w1, fmaf(g4.x, w0, acc[r]))));
        }
    }
    {
        float bb = g1b[tid];
#pragma unroll
        for (int r = 0; r < 32; r++)
            a1s[(r << 8) + tid] = fmaxf(acc[r] + bb, 0.0f);
    }
    __syncthreads();

#pragma unroll
    for (int r = 0; r < 32; r++) acc[r] = 0.0f;
#pragma unroll 1
    for (int k4 = 0; k4 < 256; k4 += 4) {
        float w0 = g2w[k4 * 256 + tid];
        float w1 = g2w[(k4 + 1) * 256 + tid];
        float w2 = g2w[(k4 + 2) * 256 + tid];
        float w3 = g2w[(k4 + 3) * 256 + tid];
#pragma unroll
        for (int r = 0; r < 32; r++) {
            float4 a4 = *(const float4*)(a1s + (r << 8) + k4);
            acc[r] = fmaf(a4.w, w3, fmaf(a4.z, w2, fmaf(a4.y, w1, fmaf(a4.x, w0, acc[r]))));
        }
    }
    __syncthreads();
    {
        float bb = g2b[tid];
#pragma unroll
        for (int r = 0; r < 32; r++)
            gs[(r << 8) + tid] = acc[r] + bb;
    }
    __syncthreads();

    const int r = tid >> 3, sub = tid & 7;
    const int c0 = sub << 5;
    float s = 0.0f;
#pragma unroll 8
    for (int c = c0; c < c0 + 32; c++) s += gs[(r << 8) + c];
    red[(r << 3) + sub] = s;
    __syncthreads();
    float mu = 0.0f;
#pragma unroll
    for (int i = 0; i < 8; i++) mu += red[(r << 3) + i];
    mu *= (1.0f / 256.0f);
    __syncthreads();
    float s2 = 0.0f;
#pragma unroll 8
    for (int c = c0; c < c0 + 32; c++) {
        float d = gs[(r << 8) + c] - mu;
        s2 += d * d;
    }
    red[(r << 3) + sub] = s2;
    __syncthreads();
    float var = 0.0f;
#pragma unroll
    for (int i = 0; i < 8; i++) var += red[(r << 3) + i];
    var *= (1.0f / 256.0f);
    float rstd = rsqrtf(var + 1e-5f);
    if (r0 + r < B) {
#pragma unroll 8
        for (int c = c0; c < c0 + 32; c++)
            out[(r0 + r) * 256 + c] =
                (gs[(r << 8) + c] - mu) * rstd * ln_g[c] + ln_b[c];
    }
}

// ---------------------------------------------------------------------------
extern "C" void kernel_launch(void* const* d_in, const int* in_sizes, int n_in,
                              void* d_out, int out_size)
{
    const float* obstacles = (const float*)d_in[0];
    const int*   lengths   = (const int*)d_in[1];
    const float* w1   = (const float*)d_in[2];
    const float* b1   = (const float*)d_in[3];
    const float* w2   = (const float*)d_in[4];
    const float* b2   = (const float*)d_in[5];
    const float* pos  = (const float*)d_in[6];
    const float* wq   = (const float*)d_in[7];
    const float* bq   = (const float*)d_in[8];
    const float* wk   = (const float*)d_in[9];
    const float* bk   = (const float*)d_in[10];
    const float* wv   = (const float*)d_in[11];
    const float* bv   = (const float*)d_in[12];
    const float* wo   = (const float*)d_in[13];
    const float* bo   = (const float*)d_in[14];
    const float* g1w  = (const float*)d_in[15];
    const float* g1b  = (const float*)d_in[16];
    const float* g2w  = (const float*)d_in[17];
    const float* g2b  = (const float*)d_in[18];
    const float* ln_g = (const float*)d_in[19];
    const float* ln_b = (const float*)d_in[20];
    float* out = (float*)d_out;

    const int B = in_sizes[1];
    const int gB = (B + 255) / 256;

    sort0_k<<<1, 32>>>();
    sort1_k<<<gB, 256>>>(lengths, B);
    sort2_k<<<1, 1>>>();
    sort3_k<<<gB, 256>>>(lengths, B);

    fold_k<<<768, 256>>>(w2, wq, wk, wv);
    posfold_k<<<192, 256>>>(pos, b2, wq, wk, wv, bq, bk, bv);
    pack_k<<<256, 256>>>(wo);

    cudaFuncSetAttribute(enc_kernel, cudaFuncAttributeMaxDynamicSharedMemorySize, SMEM_BYTES);
    enc_kernel<<<B, 1024, SMEM_BYTES>>>(obstacles, lengths, w1, b1, bo);

    cudaFuncSetAttribute(mlp_kernel, cudaFuncAttributeMaxDynamicSharedMemorySize, MLP_SMEM);
    mlp_kernel<<<(B + 31) / 32, 256, MLP_SMEM>>>(g1w, g1b, g2w, g2b, ln_g, ln_b, out, B);
}